// round 11
// baseline (speedup 1.0000x reference)
#include <cuda_runtime.h>
#include <cuda_bf16.h>
#include <cstdint>

#define T_LEN 4096
#define E_DIM 1024
#define H_DIM 2048
#define G4    8192      // 4*H
#define NTAGS 128

#define NCTA   128
#define NTHR   512
#define NWARPS 16
#define W1_ROW 8192          // bytes: 4 gates * 2048 int8
#define W2_ROW 16384         // bytes: 4 gates * 4096 int8

// SMEM layout for k2:
//   shv   [0, 4096)                      staged h1q|h2q
//   sW1   [4096, +15*8192)               W1 rows, warps 0..14
//   sW2c  [.., +16*6144)                 W2 chunks 0..2, all 16 warps, layout [warp][c][g][512]
//   sW2x  [.., +3*2048)                  W2 chunks 3..5, warp 15 only
#define SW1_OFF   4096
#define SW2C_OFF  (SW1_OFF + 15*W1_ROW)          // 126976
#define SW2X_OFF  (SW2C_OFF + 16*6144)           // 225280
#define SMEM_BYTES (SW2X_OFF + 3*2048)           // 231424 <= 232448

// ---------------- static device buffers ----------------
__device__ __align__(16) signed char g_W1q[(size_t)H_DIM * W1_ROW];   // [j][g][k]
__device__ __align__(16) signed char g_W2q[(size_t)H_DIM * W2_ROW];   // [j][g][kk]
__device__ __align__(16) float g_s1[H_DIM * 4];
__device__ __align__(16) float g_s2[H_DIM * 4];
__device__ __align__(16) float g_P[(size_t)T_LEN * G4];
__device__ __align__(16) float g_b2[G4];
__device__ __align__(16) signed char g_h1q[2][H_DIM];
__device__ __align__(16) signed char g_h2q[2][H_DIM];
__device__ __align__(16) float g_h2f[H_DIM];
__device__ __align__(16) float g_tag[NTAGS];
__device__ unsigned g_count;             // barrier arrival counter (reset each launch in k0)

// ---------------- helpers ----------------
__device__ __forceinline__ unsigned ld_acq(unsigned* a) {
    unsigned v;
    asm volatile("ld.acquire.gpu.global.u32 %0, [%1];" : "=r"(v) : "l"(a) : "memory");
    return v;
}
__device__ __forceinline__ float sigf(float x) { return 1.0f / (1.0f + __expf(-x)); }
__device__ __forceinline__ float tanhfast(float x) {
    float e = __expf(2.0f * x);
    return 1.0f - __fdividef(2.0f, e + 1.0f);
}

__device__ __forceinline__ int dotq(int acc, int4 wv, int4 hv) {
    acc = __dp4a(wv.x, hv.x, acc);
    acc = __dp4a(wv.y, hv.y, acc);
    acc = __dp4a(wv.z, hv.z, acc);
    acc = __dp4a(wv.w, hv.w, acc);
    return acc;
}

// 4-gate int8 dot from SMEM: wp row base ([g][k], gate stride GS bytes), hp = h vector
template<int NC, int GS>
__device__ __forceinline__ void dot4(const signed char* wp, const signed char* hp, int lane,
                                     int& a0, int& a1, int& a2, int& a3) {
    int off = lane * 16;
    #pragma unroll
    for (int c = 0; c < NC; c++, off += 512) {
        int4 hv = *(const int4*)(hp + off);
        int4 w0 = *(const int4*)(wp + off);
        int4 w1 = *(const int4*)(wp + GS + off);
        int4 w2 = *(const int4*)(wp + 2 * GS + off);
        int4 w3 = *(const int4*)(wp + 3 * GS + off);
        a0 = dotq(a0, w0, hv);
        a1 = dotq(a1, w1, hv);
        a2 = dotq(a2, w2, hv);
        a3 = dotq(a3, w3, hv);
    }
}

// gmem (L2) variant with ldcg: avoids thrashing the tiny post-carveout L1
template<int NC, int GS>
__device__ __forceinline__ void dot4_g(const signed char* wp, const signed char* hp, int lane,
                                       int& a0, int& a1, int& a2, int& a3) {
    int off = lane * 16;
    #pragma unroll
    for (int c = 0; c < NC; c++, off += 512) {
        int4 hv = *(const int4*)(hp + off);
        int4 w0 = __ldcg((const int4*)(wp + off));
        int4 w1 = __ldcg((const int4*)(wp + GS + off));
        int4 w2 = __ldcg((const int4*)(wp + 2 * GS + off));
        int4 w3 = __ldcg((const int4*)(wp + 3 * GS + off));
        a0 = dotq(a0, w0, hv);
        a1 = dotq(a1, w1, hv);
        a2 = dotq(a2, w2, hv);
        a3 = dotq(a3, w3, hv);
    }
}

// ---------------- K0: quantize weights (fp32 -> int8 row-scaled) + misc init ----------------
__global__ void k0_quant(const float* __restrict__ Whh1,
                         const float* __restrict__ Wih2, const float* __restrict__ Whh2,
                         const float* __restrict__ bih2, const float* __restrict__ bhh2) {
    const int tid  = blockIdx.x * blockDim.x + threadIdx.x;
    const int nt   = gridDim.x * blockDim.x;
    const int gw   = tid >> 5;
    const int nw   = nt >> 5;
    const int lane = threadIdx.x & 31;

    // layer 1: 8192 gate-rows of 2048
    for (int r = gw; r < 8192; r += nw) {
        int j = r >> 2, g = r & 3;
        const float* src = Whh1 + (size_t)(g * H_DIM + j) * H_DIM;
        float m = 0.f;
        #pragma unroll 4
        for (int c = 0; c < 16; c++) {
            float4 v = *(const float4*)(src + c * 128 + lane * 4);
            m = fmaxf(m, fmaxf(fmaxf(fabsf(v.x), fabsf(v.y)), fmaxf(fabsf(v.z), fabsf(v.w))));
        }
        #pragma unroll
        for (int o = 16; o; o >>= 1) m = fmaxf(m, __shfl_xor_sync(0xffffffffu, m, o));
        float inv = (m > 0.f) ? 127.f / m : 0.f;
        signed char* dst = g_W1q + (size_t)j * W1_ROW + g * H_DIM;
        #pragma unroll 4
        for (int c = 0; c < 16; c++) {
            float4 v = *(const float4*)(src + c * 128 + lane * 4);
            int pk = (__float2int_rn(v.x * inv) & 255)
                   | ((__float2int_rn(v.y * inv) & 255) << 8)
                   | ((__float2int_rn(v.z * inv) & 255) << 16)
                   | ((__float2int_rn(v.w * inv) & 255) << 24);
            *(int*)(dst + c * 128 + lane * 4) = pk;
        }
        if (lane == 0) g_s1[j * 4 + g] = m / 16129.f;
    }

    // layer 2: 8192 gate-rows of 4096 (Wih2 | Whh2 concat)
    for (int r = gw; r < 8192; r += nw) {
        int j = r >> 2, g = r & 3;
        const float* sA = Wih2 + (size_t)(g * H_DIM + j) * H_DIM;
        const float* sB = Whh2 + (size_t)(g * H_DIM + j) * H_DIM;
        float m = 0.f;
        #pragma unroll 4
        for (int c = 0; c < 16; c++) {
            float4 v = *(const float4*)(sA + c * 128 + lane * 4);
            m = fmaxf(m, fmaxf(fmaxf(fabsf(v.x), fabsf(v.y)), fmaxf(fabsf(v.z), fabsf(v.w))));
        }
        #pragma unroll 4
        for (int c = 0; c < 16; c++) {
            float4 v = *(const float4*)(sB + c * 128 + lane * 4);
            m = fmaxf(m, fmaxf(fmaxf(fabsf(v.x), fabsf(v.y)), fmaxf(fabsf(v.z), fabsf(v.w))));
        }
        #pragma unroll
        for (int o = 16; o; o >>= 1) m = fmaxf(m, __shfl_xor_sync(0xffffffffu, m, o));
        float inv = (m > 0.f) ? 127.f / m : 0.f;
        signed char* dst = g_W2q + (size_t)j * W2_ROW + g * 2 * H_DIM;
        #pragma unroll 4
        for (int c = 0; c < 16; c++) {
            float4 v = *(const float4*)(sA + c * 128 + lane * 4);
            int pk = (__float2int_rn(v.x * inv) & 255)
                   | ((__float2int_rn(v.y * inv) & 255) << 8)
                   | ((__float2int_rn(v.z * inv) & 255) << 16)
                   | ((__float2int_rn(v.w * inv) & 255) << 24);
            *(int*)(dst + c * 128 + lane * 4) = pk;
        }
        #pragma unroll 4
        for (int c = 0; c < 16; c++) {
            float4 v = *(const float4*)(sB + c * 128 + lane * 4);
            int pk = (__float2int_rn(v.x * inv) & 255)
                   | ((__float2int_rn(v.y * inv) & 255) << 8)
                   | ((__float2int_rn(v.z * inv) & 255) << 16)
                   | ((__float2int_rn(v.w * inv) & 255) << 24);
            *(int*)(dst + H_DIM + c * 128 + lane * 4) = pk;
        }
        if (lane == 0) g_s2[j * 4 + g] = m / 16129.f;
    }

    for (int i = tid; i < G4; i += nt) g_b2[i] = bih2[i] + bhh2[i];
    for (int i = tid; i < H_DIM; i += nt) {
        g_h1q[0][i] = 0; g_h1q[1][i] = 0;
        g_h2q[0][i] = 0; g_h2q[1][i] = 0;
    }
    if (tid == 0) g_count = 0u;
}

// ---------------- K1: P = x @ W_ih1^T + bias via bf16 tensor-core MMA (R10, unchanged) ----------------
__device__ __forceinline__ uint32_t pbf2(float lo, float hi) {
    __nv_bfloat162 h = __floats2bfloat162_rn(lo, hi);
    return *(uint32_t*)&h;
}
__device__ __forceinline__ void ldm_x4(uint32_t& r0, uint32_t& r1, uint32_t& r2, uint32_t& r3,
                                       uint32_t addr) {
    asm volatile("ldmatrix.sync.aligned.m8n8.x4.shared.b16 {%0,%1,%2,%3}, [%4];"
                 : "=r"(r0), "=r"(r1), "=r"(r2), "=r"(r3) : "r"(addr));
}
__device__ __forceinline__ void mma_bf16(float* d, const uint32_t* a, uint32_t b0, uint32_t b1) {
    asm volatile("mma.sync.aligned.m16n8k16.row.col.f32.bf16.bf16.f32 "
                 "{%0,%1,%2,%3}, {%4,%5,%6,%7}, {%8,%9}, {%0,%1,%2,%3};"
                 : "+f"(d[0]), "+f"(d[1]), "+f"(d[2]), "+f"(d[3])
                 : "r"(a[0]), "r"(a[1]), "r"(a[2]), "r"(a[3]), "r"(b0), "r"(b1));
}

#define K1_STRIDE 40   // bf16 elements per smem row (32 data + 8 pad = 80B, conflict-free)

__global__ void __launch_bounds__(256) k1_mma(const float* __restrict__ X,
                                              const float* __restrict__ W,
                                              const float* __restrict__ b1,
                                              const float* __restrict__ b2) {
    __shared__ __align__(16) __nv_bfloat16 sA[128 * K1_STRIDE];
    __shared__ __align__(16) __nv_bfloat16 sB[128 * K1_STRIDE];

    const int t    = threadIdx.x;
    const int warp = t >> 5;
    const int lane = t & 31;
    const int wm   = warp >> 2;
    const int wn   = warp & 3;
    const int m0   = blockIdx.y * 128;
    const int n0   = blockIdx.x * 128;

    const int lr = t >> 1;
    const int lc = (t & 1) * 16;

    float acc[4][4][4];
    #pragma unroll
    for (int i = 0; i < 4; i++)
        #pragma unroll
        for (int j = 0; j < 4; j++)
            #pragma unroll
            for (int q = 0; q < 4; q++) acc[i][j][q] = 0.f;

    uint32_t sA_base = (uint32_t)__cvta_generic_to_shared(sA);
    uint32_t sB_base = (uint32_t)__cvta_generic_to_shared(sB);

    for (int kt = 0; kt < E_DIM; kt += 32) {
        const float4* xs = (const float4*)(X + (size_t)(m0 + lr) * E_DIM + kt + lc);
        const float4* ws = (const float4*)(W + (size_t)(n0 + lr) * E_DIM + kt + lc);
        float4 x0 = xs[0], x1 = xs[1], x2 = xs[2], x3 = xs[3];
        float4 w0 = ws[0], w1 = ws[1], w2 = ws[2], w3 = ws[3];
        __syncthreads();
        {
            uint4 pa, pb;
            pa.x = pbf2(x0.x, x0.y); pa.y = pbf2(x0.z, x0.w);
            pa.z = pbf2(x1.x, x1.y); pa.w = pbf2(x1.z, x1.w);
            pb.x = pbf2(x2.x, x2.y); pb.y = pbf2(x2.z, x2.w);
            pb.z = pbf2(x3.x, x3.y); pb.w = pbf2(x3.z, x3.w);
            *(uint4*)(sA + lr * K1_STRIDE + lc)     = pa;
            *(uint4*)(sA + lr * K1_STRIDE + lc + 8) = pb;
            pa.x = pbf2(w0.x, w0.y); pa.y = pbf2(w0.z, w0.w);
            pa.z = pbf2(w1.x, w1.y); pa.w = pbf2(w1.z, w1.w);
            pb.x = pbf2(w2.x, w2.y); pb.y = pbf2(w2.z, w2.w);
            pb.z = pbf2(w3.x, w3.y); pb.w = pbf2(w3.z, w3.w);
            *(uint4*)(sB + lr * K1_STRIDE + lc)     = pa;
            *(uint4*)(sB + lr * K1_STRIDE + lc + 8) = pb;
        }
        __syncthreads();

        #pragma unroll
        for (int ks = 0; ks < 2; ks++) {
            uint32_t af[4][4];
            #pragma unroll
            for (int mt = 0; mt < 4; mt++) {
                int row = wm * 64 + mt * 16 + (lane & 15);
                uint32_t addr = sA_base + (uint32_t)(row * K1_STRIDE + ks * 16 + (lane >> 4) * 8) * 2u;
                ldm_x4(af[mt][0], af[mt][1], af[mt][2], af[mt][3], addr);
            }
            uint32_t bf[4][2];
            #pragma unroll
            for (int bt = 0; bt < 2; bt++) {
                int row = wn * 32 + bt * 16 + (lane & 15);
                uint32_t addr = sB_base + (uint32_t)(row * K1_STRIDE + ks * 16 + (lane >> 4) * 8) * 2u;
                uint32_t q0, q1, q2, q3;
                ldm_x4(q0, q1, q2, q3, addr);
                bf[bt * 2 + 0][0] = q0; bf[bt * 2 + 0][1] = q2;
                bf[bt * 2 + 1][0] = q1; bf[bt * 2 + 1][1] = q3;
            }
            #pragma unroll
            for (int mt = 0; mt < 4; mt++)
                #pragma unroll
                for (int nt = 0; nt < 4; nt++)
                    mma_bf16(acc[mt][nt], af[mt], bf[nt][0], bf[nt][1]);
        }
    }

    #pragma unroll
    for (int nt = 0; nt < 4; nt++) {
        int col = n0 + wn * 32 + nt * 8 + (lane & 3) * 2;
        float bc0 = __ldg(&b1[col])     + __ldg(&b2[col]);
        float bc1 = __ldg(&b1[col + 1]) + __ldg(&b2[col + 1]);
        #pragma unroll
        for (int mt = 0; mt < 4; mt++) {
            int row = m0 + wm * 64 + mt * 16 + (lane >> 2);
            float2 v0 = make_float2(acc[mt][nt][0] + bc0, acc[mt][nt][1] + bc1);
            float2 v1 = make_float2(acc[mt][nt][2] + bc0, acc[mt][nt][3] + bc1);
            __stcs((float2*)(g_P + (size_t)row * G4 + col), v0);
            __stcs((float2*)(g_P + (size_t)(row + 8) * G4 + col), v1);
        }
    }
}

// ---------------- K2: persistent int8 recurrent kernel, uniform weight split ----------------
__global__ void __launch_bounds__(NTHR, 1) k2_recur() {
    extern __shared__ __align__(16) signed char smem[];
    signed char* shv = smem;                         // 4096: h1q(2048) | h2q(2048)

    const int tid  = threadIdx.x;
    const int warp = tid >> 5;
    const int lane = tid & 31;
    const int w    = blockIdx.x * NWARPS + warp;     // owned h-row, both layers

    // --- pin weights in SMEM ---
    // W1 rows for warps 0..14
    if (warp < 15) {
        const int4* src = (const int4*)(g_W1q + (size_t)w * W1_ROW);
        int4* dst = (int4*)(smem + SW1_OFF + (size_t)warp * W1_ROW);
        #pragma unroll
        for (int i = 0; i < 16; i++) dst[lane + i * 32] = src[lane + i * 32];
    }
    // W2 chunks 0..2 for all warps: layout [warp][c][g][512]
    {
        const signed char* src = g_W2q + (size_t)w * W2_ROW;
        signed char* dst = smem + SW2C_OFF + warp * 6144;
        #pragma unroll
        for (int c = 0; c < 3; c++)
            #pragma unroll
            for (int g = 0; g < 4; g++)
                *(int4*)(dst + c * 2048 + g * 512 + lane * 16) =
                    *(const int4*)(src + g * 4096 + c * 512 + lane * 16);
    }
    // W2 chunks 3..5 for warp 15
    if (warp == 15) {
        const signed char* src = g_W2q + (size_t)w * W2_ROW;
        signed char* dst = smem + SW2X_OFF;
        #pragma unroll
        for (int c = 3; c < 6; c++)
            #pragma unroll
            for (int g = 0; g < 4; g++)
                *(int4*)(dst + (c - 3) * 2048 + g * 512 + lane * 16) =
                    *(const int4*)(src + g * 4096 + c * 512 + lane * 16);
    }

    const float4 fs1 = *(const float4*)(g_s1 + w * 4);
    const float4 fs2 = *(const float4*)(g_s2 + w * 4);
    const float bi = g_b2[w], bf = g_b2[w + H_DIM], bg = g_b2[w + 2*H_DIM], bo = g_b2[w + 3*H_DIM];

    float c1 = 0.f, c2 = 0.f;
    const signed char* wg2 = g_W2q + (size_t)w * W2_ROW;   // gmem W2 row (gate stride 4096)

    for (int p = 0; p <= T_LEN; p++) {
        // prefetch this step's P early (independent of the staged h)
        float p0 = 0.f, p1 = 0.f, p2 = 0.f, p3 = 0.f;
        if (lane == 0 && p < T_LEN) {
            size_t pb = (size_t)p * G4 + w;
            p0 = __ldcs(&g_P[pb]);
            p1 = __ldcs(&g_P[pb + H_DIM]);
            p2 = __ldcs(&g_P[pb + 2*H_DIM]);
            p3 = __ldcs(&g_P[pb + 3*H_DIM]);
        }

        // prefetch first two gmem W2 chunks at phase top: LDG flight overlaps
        // stage + sync + layer-1 compute. (warps<15: chunks 3,4; warp15: chunks 6,7)
        int4 f0g0, f0g1, f0g2, f0g3, f1g0, f1g1, f1g2, f1g3;
        const int cFirst = (warp < 15) ? 3 : 6;
        if (p >= 1) {
            const signed char* b0 = wg2 + cFirst * 512 + lane * 16;
            f0g0 = __ldcg((const int4*)(b0));
            f0g1 = __ldcg((const int4*)(b0 + 4096));
            f0g2 = __ldcg((const int4*)(b0 + 8192));
            f0g3 = __ldcg((const int4*)(b0 + 12288));
            const signed char* b1p = b0 + 512;
            f1g0 = __ldcg((const int4*)(b1p));
            f1g1 = __ldcg((const int4*)(b1p + 4096));
            f1g2 = __ldcg((const int4*)(b1p + 8192));
            f1g3 = __ldcg((const int4*)(b1p + 12288));
        }

        // stage h vectors: shv[0:2048]=h1q_{p-1}, shv[2048:4096]=h2q_{p-2}
        {
            const int2* s1 = (const int2*)g_h1q[p & 1];
            const int2* s2 = (const int2*)g_h2q[(p + 1) & 1];
            if (tid < 256) ((int2*)shv)[tid] = __ldcg(s1 + tid);
            else           ((int2*)shv)[tid] = __ldcg(s2 + (tid - 256));
        }
        __syncthreads();

        // -------- layer 1, step t = p --------
        if (p < T_LEN) {
            int a0 = 0, a1 = 0, a2 = 0, a3 = 0;
            if (warp < 15)
                dot4<4, H_DIM>(smem + SW1_OFF + (size_t)warp * W1_ROW, shv, lane, a0, a1, a2, a3);
            else
                dot4_g<4, H_DIM>(g_W1q + (size_t)w * W1_ROW, shv, lane, a0, a1, a2, a3);
            a0 = __reduce_add_sync(0xffffffffu, a0);
            a1 = __reduce_add_sync(0xffffffffu, a1);
            a2 = __reduce_add_sync(0xffffffffu, a2);
            a3 = __reduce_add_sync(0xffffffffu, a3);
            if (lane == 0) {
                float gi  = (float)a0 * fs1.x + p0;
                float gf_ = (float)a1 * fs1.y + p1;
                float gg  = (float)a2 * fs1.z + p2;
                float go_ = (float)a3 * fs1.w + p3;
                c1 = sigf(gf_) * c1 + sigf(gi) * tanhfast(gg);
                float h = sigf(go_) * tanhfast(c1);
                g_h1q[(p + 1) & 1][w] = (signed char)__float2int_rn(h * 127.f);
            }
        }

        // -------- layer 2, step t = p-1 (input [h1q_{p-1} ; h2q_{p-2}] = shv) --------
        if (p >= 1) {
            int a0 = 0, a1 = 0, a2 = 0, a3 = 0;
            const int off0 = lane * 16;

            // cached chunks 0..2 (all warps), layout [c][g][512]
            {
                const signed char* wc = smem + SW2C_OFF + warp * 6144;
                #pragma unroll
                for (int c = 0; c < 3; c++) {
                    int4 hv = *(const int4*)(shv + c * 512 + off0);
                    const signed char* cb = wc + c * 2048 + off0;
                    int4 w0 = *(const int4*)(cb);
                    int4 w1 = *(const int4*)(cb + 512);
                    int4 w2 = *(const int4*)(cb + 1024);
                    int4 w3 = *(const int4*)(cb + 1536);
                    a0 = dotq(a0, w0, hv);
                    a1 = dotq(a1, w1, hv);
                    a2 = dotq(a2, w2, hv);
                    a3 = dotq(a3, w3, hv);
                }
            }

            if (warp < 15) {
                // gmem chunks 3..7 with 2-chunk lookahead (3,4 already in flight)
                #pragma unroll
                for (int c = 3; c <= 7; c++) {
                    int4 n0, n1, n2, n3;
                    if (c + 2 <= 7) {
                        const signed char* nb = wg2 + (c + 2) * 512 + off0;
                        n0 = __ldcg((const int4*)(nb));
                        n1 = __ldcg((const int4*)(nb + 4096));
                        n2 = __ldcg((const int4*)(nb + 8192));
                        n3 = __ldcg((const int4*)(nb + 12288));
                    }
                    int4 hv = *(const int4*)(shv + c * 512 + off0);
                    a0 = dotq(a0, f0g0, hv);
                    a1 = dotq(a1, f0g1, hv);
                    a2 = dotq(a2, f0g2, hv);
                    a3 = dotq(a3, f0g3, hv);
                    f0g0 = f1g0; f0g1 = f1g1; f0g2 = f1g2; f0g3 = f1g3;
                    if (c + 2 <= 7) { f1g0 = n0; f1g1 = n1; f1g2 = n2; f1g3 = n3; }
                }
            } else {
                // warp 15: cached chunks 3..5 from sW2x
                #pragma unroll
                for (int c = 3; c < 6; c++) {
                    int4 hv = *(const int4*)(shv + c * 512 + off0);
                    const signed char* cb = smem + SW2X_OFF + (c - 3) * 2048 + off0;
                    int4 w0 = *(const int4*)(cb);
                    int4 w1 = *(const int4*)(cb + 512);
                    int4 w2 = *(const int4*)(cb + 1024);
                    int4 w3 = *(const int4*)(cb + 1536);
                    a0 = dotq(a0, w0, hv);
                    a1 = dotq(a1, w1, hv);
                    a2 = dotq(a2, w2, hv);
                    a3 = dotq(a3, w3, hv);
                }
                // gmem chunks 6,7 (prefetched at phase top)
                {
                    int4 hv = *(const int4*)(shv + 6 * 512 + off0);
                    a0 = dotq(a0, f0g0, hv);
                    a1 = dotq(a1, f0g1, hv);
                    a2 = dotq(a2, f0g2, hv);
                    a3 = dotq(a3, f0g3, hv);
                    hv = *(const int4*)(shv + 7 * 512 + off0);
                    a0 = dotq(a0, f1g0, hv);
                    a1 = dotq(a1, f1g1, hv);
                    a2 = dotq(a2, f1g2, hv);
                    a3 = dotq(a3, f1g3, hv);
                }
            }

            a0 = __reduce_add_sync(0xffffffffu, a0);
            a1 = __reduce_add_sync(0xffffffffu, a1);
            a2 = __reduce_add_sync(0xffffffffu, a2);
            a3 = __reduce_add_sync(0xffffffffu, a3);
            if (lane == 0) {
                float gi  = (float)a0 * fs2.x + bi;
                float gf_ = (float)a1 * fs2.y + bf;
                float gg  = (float)a2 * fs2.z + bg;
                float go_ = (float)a3 * fs2.w + bo;
                c2 = sigf(gf_) * c2 + sigf(gi) * tanhfast(gg);
                float h = sigf(go_) * tanhfast(c2);
                g_h2q[p & 1][w] = (signed char)__float2int_rn(h * 127.f);
                if (p == T_LEN) g_h2f[w] = h;
            }
        }

        // -------- grid barrier: fence + atomicAdd arrive, single-word acquire poll --------
        __syncthreads();
        if (tid == 0) {
            __threadfence();                         // release: publish h-state stores
            atomicAdd(&g_count, 1u);
            unsigned tgt = (unsigned)(p + 1) * (unsigned)NCTA;
            while (ld_acq(&g_count) < tgt) { }
        }
        __syncthreads();
    }
}

// ---------------- K3a: tag_space = h2 @ W_out^T + b_out (one block per tag) ----------------
__global__ void k3a(const float* __restrict__ Wout, const float* __restrict__ bout) {
    __shared__ float red[256];
    const int b = blockIdx.x, t = threadIdx.x;
    float acc = 0.f;
    #pragma unroll
    for (int c = 0; c < 2; c++) {
        float4 wv = *(const float4*)(Wout + (size_t)b * H_DIM + c * 1024 + t * 4);
        float4 hv = *(const float4*)(g_h2f + c * 1024 + t * 4);
        acc += wv.x * hv.x + wv.y * hv.y + wv.z * hv.z + wv.w * hv.w;
    }
    red[t] = acc;
    __syncthreads();
    #pragma unroll
    for (int s = 128; s; s >>= 1) {
        if (t < s) red[t] += red[t + s];
        __syncthreads();
    }
    if (t == 0) g_tag[b] = red[0] + bout[b];
}

// ---------------- K3b: log_softmax ----------------
__global__ void k3b(float* __restrict__ out) {
    __shared__ float st[NTAGS];
    __shared__ float m_s, l_s;
    const int t = threadIdx.x;
    float v = g_tag[t];
    st[t] = v;
    __syncthreads();
    if (t == 0) {
        float m = st[0];
        for (int i = 1; i < NTAGS; i++) m = fmaxf(m, st[i]);
        float s = 0.f;
        for (int i = 0; i < NTAGS; i++) s += expf(st[i] - m);
        m_s = m;
        l_s = logf(s);
    }
    __syncthreads();
    out[t] = v - m_s - l_s;
}

// ---------------- launch ----------------
extern "C" void kernel_launch(void* const* d_in, const int* in_sizes, int n_in,
                              void* d_out, int out_size) {
    const float* x    = (const float*)d_in[0];
    const float* Wih1 = (const float*)d_in[1];
    const float* Whh1 = (const float*)d_in[2];
    const float* bih1 = (const float*)d_in[3];
    const float* bhh1 = (const float*)d_in[4];
    const float* Wih2 = (const float*)d_in[5];
    const float* Whh2 = (const float*)d_in[6];
    const float* bih2 = (const float*)d_in[7];
    const float* bhh2 = (const float*)d_in[8];
    const float* Wout = (const float*)d_in[9];
    const float* bout = (const float*)d_in[10];

    cudaFuncSetAttribute(k2_recur, cudaFuncAttributeMaxDynamicSharedMemorySize, SMEM_BYTES);

    k0_quant<<<512, 256>>>(Whh1, Wih2, Whh2, bih2, bhh2);

    dim3 g1(G4 / 128, T_LEN / 128);
    k1_mma<<<g1, 256>>>(x, Wih1, bih1, bhh1);

    k2_recur<<<NCTA, NTHR, SMEM_BYTES>>>();

    k3a<<<NTAGS, 256>>>(Wout, bout);
    k3b<<<1, NTAGS>>>((float*)d_out);
}

// round 12
// speedup vs baseline: 1.1005x; 1.1005x over previous
#include <cuda_runtime.h>
#include <cuda_bf16.h>
#include <cstdint>

#define T_LEN 4096
#define E_DIM 1024
#define H_DIM 2048
#define G4    8192      // 4*H
#define NTAGS 128

#define NCTA   128
#define NTHR   512
#define NWARPS 16
#define W1_ROW 8192          // bytes: 4 gates * 2048 int8
#define W2_ROW 16384         // bytes: 4 gates * 4096 int8

// k2 SMEM layout:
//   shv  [0, 4096)                       staged h1q|h2q
//   sW1  [4096, +15*8192)                W1 rows, warps 0..14
//   sW2  [126976, +8*12288)              W2 chunks 2..7 ([g][c-2] layout, gate stride 3072), warps 0..7
#define SW1_OFF   4096
#define SW2_OFF   (SW1_OFF + 15*W1_ROW)          // 126976
#define SMEM_BYTES (SW2_OFF + 8*12288)           // 225280

// ---------------- static device buffers ----------------
__device__ __align__(16) signed char g_W1q[(size_t)H_DIM * W1_ROW];   // [j][g][k]
__device__ __align__(16) signed char g_W2q[(size_t)H_DIM * W2_ROW];   // [j][g][kk]
__device__ __align__(16) float g_s1[H_DIM * 4];
__device__ __align__(16) float g_s2[H_DIM * 4];
__device__ __align__(16) float g_P[(size_t)T_LEN * G4];
__device__ __align__(16) float g_b2[G4];
__device__ __align__(16) signed char g_h1q[2][H_DIM];
__device__ __align__(16) signed char g_h2q[2][H_DIM];
__device__ __align__(16) float g_h2f[H_DIM];
__device__ __align__(16) float g_tag[NTAGS];
__device__ unsigned g_count;             // barrier arrival counter (reset each launch in k0)

// ---------------- helpers ----------------
__device__ __forceinline__ unsigned ld_acq(unsigned* a) {
    unsigned v;
    asm volatile("ld.acquire.gpu.global.u32 %0, [%1];" : "=r"(v) : "l"(a) : "memory");
    return v;
}
__device__ __forceinline__ float sigf(float x) { return 1.0f / (1.0f + __expf(-x)); }
__device__ __forceinline__ float tanhfast(float x) {
    float e = __expf(2.0f * x);
    return 1.0f - __fdividef(2.0f, e + 1.0f);
}

__device__ __forceinline__ int dotq(int acc, int4 wv, int4 hv) {
    acc = __dp4a(wv.x, hv.x, acc);
    acc = __dp4a(wv.y, hv.y, acc);
    acc = __dp4a(wv.z, hv.z, acc);
    acc = __dp4a(wv.w, hv.w, acc);
    return acc;
}

// 4-gate int8 dot: wp = row base ([g][k] layout, gate stride GS bytes), hp = h vector
// NC chunks of 512 bytes; lane covers bytes [lane*16 + c*512, +16)
template<int NC, int GS>
__device__ __forceinline__ void dot4(const signed char* wp, const signed char* hp, int lane,
                                     int& a0, int& a1, int& a2, int& a3) {
    int off = lane * 16;
    #pragma unroll
    for (int c = 0; c < NC; c++, off += 512) {
        int4 hv = *(const int4*)(hp + off);
        int4 w0 = *(const int4*)(wp + off);
        int4 w1 = *(const int4*)(wp + GS + off);
        int4 w2 = *(const int4*)(wp + 2 * GS + off);
        int4 w3 = *(const int4*)(wp + 3 * GS + off);
        a0 = dotq(a0, w0, hv);
        a1 = dotq(a1, w1, hv);
        a2 = dotq(a2, w2, hv);
        a3 = dotq(a3, w3, hv);
    }
}

// ---------------- K0: quantize weights (fp32 -> int8 row-scaled) + misc init ----------------
__global__ void k0_quant(const float* __restrict__ Whh1,
                         const float* __restrict__ Wih2, const float* __restrict__ Whh2,
                         const float* __restrict__ bih2, const float* __restrict__ bhh2) {
    const int tid  = blockIdx.x * blockDim.x + threadIdx.x;
    const int nt   = gridDim.x * blockDim.x;
    const int gw   = tid >> 5;
    const int nw   = nt >> 5;
    const int lane = threadIdx.x & 31;

    // layer 1: 8192 gate-rows of 2048
    for (int r = gw; r < 8192; r += nw) {
        int j = r >> 2, g = r & 3;
        const float* src = Whh1 + (size_t)(g * H_DIM + j) * H_DIM;
        float m = 0.f;
        #pragma unroll 4
        for (int c = 0; c < 16; c++) {
            float4 v = *(const float4*)(src + c * 128 + lane * 4);
            m = fmaxf(m, fmaxf(fmaxf(fabsf(v.x), fabsf(v.y)), fmaxf(fabsf(v.z), fabsf(v.w))));
        }
        #pragma unroll
        for (int o = 16; o; o >>= 1) m = fmaxf(m, __shfl_xor_sync(0xffffffffu, m, o));
        float inv = (m > 0.f) ? 127.f / m : 0.f;
        signed char* dst = g_W1q + (size_t)j * W1_ROW + g * H_DIM;
        #pragma unroll 4
        for (int c = 0; c < 16; c++) {
            float4 v = *(const float4*)(src + c * 128 + lane * 4);
            int pk = (__float2int_rn(v.x * inv) & 255)
                   | ((__float2int_rn(v.y * inv) & 255) << 8)
                   | ((__float2int_rn(v.z * inv) & 255) << 16)
                   | ((__float2int_rn(v.w * inv) & 255) << 24);
            *(int*)(dst + c * 128 + lane * 4) = pk;
        }
        if (lane == 0) g_s1[j * 4 + g] = m / 16129.f;
    }

    // layer 2: 8192 gate-rows of 4096 (Wih2 | Whh2 concat)
    for (int r = gw; r < 8192; r += nw) {
        int j = r >> 2, g = r & 3;
        const float* sA = Wih2 + (size_t)(g * H_DIM + j) * H_DIM;
        const float* sB = Whh2 + (size_t)(g * H_DIM + j) * H_DIM;
        float m = 0.f;
        #pragma unroll 4
        for (int c = 0; c < 16; c++) {
            float4 v = *(const float4*)(sA + c * 128 + lane * 4);
            m = fmaxf(m, fmaxf(fmaxf(fabsf(v.x), fabsf(v.y)), fmaxf(fabsf(v.z), fabsf(v.w))));
        }
        #pragma unroll 4
        for (int c = 0; c < 16; c++) {
            float4 v = *(const float4*)(sB + c * 128 + lane * 4);
            m = fmaxf(m, fmaxf(fmaxf(fabsf(v.x), fabsf(v.y)), fmaxf(fabsf(v.z), fabsf(v.w))));
        }
        #pragma unroll
        for (int o = 16; o; o >>= 1) m = fmaxf(m, __shfl_xor_sync(0xffffffffu, m, o));
        float inv = (m > 0.f) ? 127.f / m : 0.f;
        signed char* dst = g_W2q + (size_t)j * W2_ROW + g * 2 * H_DIM;
        #pragma unroll 4
        for (int c = 0; c < 16; c++) {
            float4 v = *(const float4*)(sA + c * 128 + lane * 4);
            int pk = (__float2int_rn(v.x * inv) & 255)
                   | ((__float2int_rn(v.y * inv) & 255) << 8)
                   | ((__float2int_rn(v.z * inv) & 255) << 16)
                   | ((__float2int_rn(v.w * inv) & 255) << 24);
            *(int*)(dst + c * 128 + lane * 4) = pk;
        }
        #pragma unroll 4
        for (int c = 0; c < 16; c++) {
            float4 v = *(const float4*)(sB + c * 128 + lane * 4);
            int pk = (__float2int_rn(v.x * inv) & 255)
                   | ((__float2int_rn(v.y * inv) & 255) << 8)
                   | ((__float2int_rn(v.z * inv) & 255) << 16)
                   | ((__float2int_rn(v.w * inv) & 255) << 24);
            *(int*)(dst + H_DIM + c * 128 + lane * 4) = pk;
        }
        if (lane == 0) g_s2[j * 4 + g] = m / 16129.f;
    }

    for (int i = tid; i < G4; i += nt) g_b2[i] = bih2[i] + bhh2[i];
    for (int i = tid; i < H_DIM; i += nt) {
        g_h1q[0][i] = 0; g_h1q[1][i] = 0;
        g_h2q[0][i] = 0; g_h2q[1][i] = 0;
    }
    if (tid == 0) g_count = 0u;
}

// ---------------- K1: P = x @ W_ih1^T + bias via bf16 tensor-core MMA (R10, unchanged) ----------------
__device__ __forceinline__ uint32_t pbf2(float lo, float hi) {
    __nv_bfloat162 h = __floats2bfloat162_rn(lo, hi);
    return *(uint32_t*)&h;
}
__device__ __forceinline__ void ldm_x4(uint32_t& r0, uint32_t& r1, uint32_t& r2, uint32_t& r3,
                                       uint32_t addr) {
    asm volatile("ldmatrix.sync.aligned.m8n8.x4.shared.b16 {%0,%1,%2,%3}, [%4];"
                 : "=r"(r0), "=r"(r1), "=r"(r2), "=r"(r3) : "r"(addr));
}
__device__ __forceinline__ void mma_bf16(float* d, const uint32_t* a, uint32_t b0, uint32_t b1) {
    asm volatile("mma.sync.aligned.m16n8k16.row.col.f32.bf16.bf16.f32 "
                 "{%0,%1,%2,%3}, {%4,%5,%6,%7}, {%8,%9}, {%0,%1,%2,%3};"
                 : "+f"(d[0]), "+f"(d[1]), "+f"(d[2]), "+f"(d[3])
                 : "r"(a[0]), "r"(a[1]), "r"(a[2]), "r"(a[3]), "r"(b0), "r"(b1));
}

#define K1_STRIDE 40   // bf16 elements per smem row (32 data + 8 pad = 80B, conflict-free)

__global__ void __launch_bounds__(256) k1_mma(const float* __restrict__ X,
                                              const float* __restrict__ W,
                                              const float* __restrict__ b1,
                                              const float* __restrict__ b2) {
    __shared__ __align__(16) __nv_bfloat16 sA[128 * K1_STRIDE];
    __shared__ __align__(16) __nv_bfloat16 sB[128 * K1_STRIDE];

    const int t    = threadIdx.x;
    const int warp = t >> 5;
    const int lane = t & 31;
    const int wm   = warp >> 2;
    const int wn   = warp & 3;
    const int m0   = blockIdx.y * 128;
    const int n0   = blockIdx.x * 128;

    const int lr = t >> 1;
    const int lc = (t & 1) * 16;

    float acc[4][4][4];
    #pragma unroll
    for (int i = 0; i < 4; i++)
        #pragma unroll
        for (int j = 0; j < 4; j++)
            #pragma unroll
            for (int q = 0; q < 4; q++) acc[i][j][q] = 0.f;

    uint32_t sA_base = (uint32_t)__cvta_generic_to_shared(sA);
    uint32_t sB_base = (uint32_t)__cvta_generic_to_shared(sB);

    for (int kt = 0; kt < E_DIM; kt += 32) {
        const float4* xs = (const float4*)(X + (size_t)(m0 + lr) * E_DIM + kt + lc);
        const float4* ws = (const float4*)(W + (size_t)(n0 + lr) * E_DIM + kt + lc);
        float4 x0 = xs[0], x1 = xs[1], x2 = xs[2], x3 = xs[3];
        float4 w0 = ws[0], w1 = ws[1], w2 = ws[2], w3 = ws[3];
        __syncthreads();
        {
            uint4 pa, pb;
            pa.x = pbf2(x0.x, x0.y); pa.y = pbf2(x0.z, x0.w);
            pa.z = pbf2(x1.x, x1.y); pa.w = pbf2(x1.z, x1.w);
            pb.x = pbf2(x2.x, x2.y); pb.y = pbf2(x2.z, x2.w);
            pb.z = pbf2(x3.x, x3.y); pb.w = pbf2(x3.z, x3.w);
            *(uint4*)(sA + lr * K1_STRIDE + lc)     = pa;
            *(uint4*)(sA + lr * K1_STRIDE + lc + 8) = pb;
            pa.x = pbf2(w0.x, w0.y); pa.y = pbf2(w0.z, w0.w);
            pa.z = pbf2(w1.x, w1.y); pa.w = pbf2(w1.z, w1.w);
            pb.x = pbf2(w2.x, w2.y); pb.y = pbf2(w2.z, w2.w);
            pb.z = pbf2(w3.x, w3.y); pb.w = pbf2(w3.z, w3.w);
            *(uint4*)(sB + lr * K1_STRIDE + lc)     = pa;
            *(uint4*)(sB + lr * K1_STRIDE + lc + 8) = pb;
        }
        __syncthreads();

        #pragma unroll
        for (int ks = 0; ks < 2; ks++) {
            uint32_t af[4][4];
            #pragma unroll
            for (int mt = 0; mt < 4; mt++) {
                int row = wm * 64 + mt * 16 + (lane & 15);
                uint32_t addr = sA_base + (uint32_t)(row * K1_STRIDE + ks * 16 + (lane >> 4) * 8) * 2u;
                ldm_x4(af[mt][0], af[mt][1], af[mt][2], af[mt][3], addr);
            }
            uint32_t bf[4][2];
            #pragma unroll
            for (int bt = 0; bt < 2; bt++) {
                int row = wn * 32 + bt * 16 + (lane & 15);
                uint32_t addr = sB_base + (uint32_t)(row * K1_STRIDE + ks * 16 + (lane >> 4) * 8) * 2u;
                uint32_t q0, q1, q2, q3;
                ldm_x4(q0, q1, q2, q3, addr);
                bf[bt * 2 + 0][0] = q0; bf[bt * 2 + 0][1] = q2;
                bf[bt * 2 + 1][0] = q1; bf[bt * 2 + 1][1] = q3;
            }
            #pragma unroll
            for (int mt = 0; mt < 4; mt++)
                #pragma unroll
                for (int nt = 0; nt < 4; nt++)
                    mma_bf16(acc[mt][nt], af[mt], bf[nt][0], bf[nt][1]);
        }
    }

    #pragma unroll
    for (int nt = 0; nt < 4; nt++) {
        int col = n0 + wn * 32 + nt * 8 + (lane & 3) * 2;
        float bc0 = __ldg(&b1[col])     + __ldg(&b2[col]);
        float bc1 = __ldg(&b1[col + 1]) + __ldg(&b2[col + 1]);
        #pragma unroll
        for (int mt = 0; mt < 4; mt++) {
            int row = m0 + wm * 64 + mt * 16 + (lane >> 2);
            float2 v0 = make_float2(acc[mt][nt][0] + bc0, acc[mt][nt][1] + bc1);
            float2 v1 = make_float2(acc[mt][nt][2] + bc0, acc[mt][nt][3] + bc1);
            __stcs((float2*)(g_P + (size_t)row * G4 + col), v0);
            __stcs((float2*)(g_P + (size_t)(row + 8) * G4 + col), v1);
        }
    }
}

// ---------------- K2: persistent int8 recurrent kernel, register-cached W2 head ----------------
__global__ void __launch_bounds__(NTHR, 1) k2_recur() {
    extern __shared__ __align__(16) signed char smem[];
    signed char* shv = smem;                         // 4096: h1q(2048) | h2q(2048)

    const int tid  = threadIdx.x;
    const int warp = tid >> 5;
    const int lane = tid & 31;
    const int w    = blockIdx.x * NWARPS + warp;     // owned h-row, both layers

    const signed char* wg1 = g_W1q + (size_t)w * W1_ROW;
    const signed char* wg2 = g_W2q + (size_t)w * W2_ROW;

    // pin W1 rows (warps 0..14)
    if (warp < 15) {
        const int4* src = (const int4*)wg1;
        int4* dst = (int4*)(smem + SW1_OFF + (size_t)warp * W1_ROW);
        #pragma unroll
        for (int i = 0; i < 16; i++) dst[lane + i * 32] = src[lane + i * 32];
    }
    // pin W2 chunks 2..7 for warps 0..7 (gate stride 3072 in SMEM)
    if (warp < 8) {
        signed char* dst = smem + SW2_OFF + (size_t)warp * 12288;
        #pragma unroll
        for (int g = 0; g < 4; g++)
            #pragma unroll
            for (int c = 2; c < 8; c++)
                *(int4*)(dst + g * 3072 + (c - 2) * 512 + lane * 16) =
                    *(const int4*)(wg2 + g * 4096 + c * 512 + lane * 16);
    }
    // ALL warps: hold W2 chunks 0,1 permanently in registers (8 int4 = 32 regs)
    int4 rw0 = *(const int4*)(wg2 + 0 * 4096 + lane * 16);
    int4 rw1 = *(const int4*)(wg2 + 1 * 4096 + lane * 16);
    int4 rw2 = *(const int4*)(wg2 + 2 * 4096 + lane * 16);
    int4 rw3 = *(const int4*)(wg2 + 3 * 4096 + lane * 16);
    int4 rv0 = *(const int4*)(wg2 + 0 * 4096 + 512 + lane * 16);
    int4 rv1 = *(const int4*)(wg2 + 1 * 4096 + 512 + lane * 16);
    int4 rv2 = *(const int4*)(wg2 + 2 * 4096 + 512 + lane * 16);
    int4 rv3 = *(const int4*)(wg2 + 3 * 4096 + 512 + lane * 16);

    const float4 fs1 = *(const float4*)(g_s1 + w * 4);
    const float4 fs2 = *(const float4*)(g_s2 + w * 4);
    const float bi = g_b2[w], bf = g_b2[w + H_DIM], bg = g_b2[w + 2*H_DIM], bo = g_b2[w + 3*H_DIM];

    float c1 = 0.f, c2 = 0.f;

    for (int p = 0; p <= T_LEN; p++) {
        // prefetch this step's P early (independent of the staged h)
        float p0 = 0.f, p1 = 0.f, p2 = 0.f, p3 = 0.f;
        if (lane == 0 && p < T_LEN) {
            size_t pb = (size_t)p * G4 + w;
            p0 = __ldcs(&g_P[pb]);
            p1 = __ldcs(&g_P[pb + H_DIM]);
            p2 = __ldcs(&g_P[pb + 2*H_DIM]);
            p3 = __ldcs(&g_P[pb + 3*H_DIM]);
        }

        // stage h vectors: shv[0:2048]=h1q_{p-1}, shv[2048:4096]=h2q_{p-2}
        {
            const int2* s1 = (const int2*)g_h1q[p & 1];
            const int2* s2 = (const int2*)g_h2q[(p + 1) & 1];
            if (tid < 256) ((int2*)shv)[tid] = __ldcg(s1 + tid);
            else           ((int2*)shv)[tid] = __ldcg(s2 + (tid - 256));
        }
        __syncthreads();

        // -------- layer 1, step t = p --------
        if (p < T_LEN) {
            int a0 = 0, a1 = 0, a2 = 0, a3 = 0;
            if (warp < 15)
                dot4<4, H_DIM>(smem + SW1_OFF + (size_t)warp * W1_ROW, shv, lane, a0, a1, a2, a3);
            else
                dot4<4, H_DIM>(wg1, shv, lane, a0, a1, a2, a3);
            a0 = __reduce_add_sync(0xffffffffu, a0);
            a1 = __reduce_add_sync(0xffffffffu, a1);
            a2 = __reduce_add_sync(0xffffffffu, a2);
            a3 = __reduce_add_sync(0xffffffffu, a3);
            if (lane == 0) {
                float gi  = (float)a0 * fs1.x + p0;
                float gf_ = (float)a1 * fs1.y + p1;
                float gg  = (float)a2 * fs1.z + p2;
                float go_ = (float)a3 * fs1.w + p3;
                c1 = sigf(gf_) * c1 + sigf(gi) * tanhfast(gg);
                float h = sigf(go_) * tanhfast(c1);
                g_h1q[(p + 1) & 1][w] = (signed char)__float2int_rn(h * 127.f);
            }
        }

        // -------- layer 2, step t = p-1 (input [h1q_{p-1} ; h2q_{p-2}] = shv) --------
        if (p >= 1) {
            int a0 = 0, a1 = 0, a2 = 0, a3 = 0;
            const int off0 = lane * 16;
            // chunks 0,1 from registers
            {
                int4 hv0 = *(const int4*)(shv + off0);
                int4 hv1 = *(const int4*)(shv + 512 + off0);
                a0 = dotq(a0, rw0, hv0);
                a1 = dotq(a1, rw1, hv0);
                a2 = dotq(a2, rw2, hv0);
                a3 = dotq(a3, rw3, hv0);
                a0 = dotq(a0, rv0, hv1);
                a1 = dotq(a1, rv1, hv1);
                a2 = dotq(a2, rv2, hv1);
                a3 = dotq(a3, rv3, hv1);
            }
            // chunks 2..7: SMEM for warps 0..7, gmem for warps 8..15
            if (warp < 8)
                dot4<6, 3072>(smem + SW2_OFF + (size_t)warp * 12288, shv + 1024, lane, a0, a1, a2, a3);
            else
                dot4<6, 2*H_DIM>(wg2 + 1024, shv + 1024, lane, a0, a1, a2, a3);
            a0 = __reduce_add_sync(0xffffffffu, a0);
            a1 = __reduce_add_sync(0xffffffffu, a1);
            a2 = __reduce_add_sync(0xffffffffu, a2);
            a3 = __reduce_add_sync(0xffffffffu, a3);
            if (lane == 0) {
                float gi  = (float)a0 * fs2.x + bi;
                float gf_ = (float)a1 * fs2.y + bf;
                float gg  = (float)a2 * fs2.z + bg;
                float go_ = (float)a3 * fs2.w + bo;
                c2 = sigf(gf_) * c2 + sigf(gi) * tanhfast(gg);
                float h = sigf(go_) * tanhfast(c2);
                g_h2q[p & 1][w] = (signed char)__float2int_rn(h * 127.f);
                if (p == T_LEN) g_h2f[w] = h;
            }
        }

        // -------- grid barrier: fence + atomicAdd arrive, single-word acquire poll --------
        __syncthreads();
        if (tid == 0) {
            __threadfence();                         // release: publish h-state stores
            atomicAdd(&g_count, 1u);
            unsigned tgt = (unsigned)(p + 1) * (unsigned)NCTA;
            while (ld_acq(&g_count) < tgt) { }
        }
        __syncthreads();
    }
}

// ---------------- K3a: tag_space = h2 @ W_out^T + b_out (one block per tag) ----------------
__global__ void k3a(const float* __restrict__ Wout, const float* __restrict__ bout) {
    __shared__ float red[256];
    const int b = blockIdx.x, t = threadIdx.x;
    float acc = 0.f;
    #pragma unroll
    for (int c = 0; c < 2; c++) {
        float4 wv = *(const float4*)(Wout + (size_t)b * H_DIM + c * 1024 + t * 4);
        float4 hv = *(const float4*)(g_h2f + c * 1024 + t * 4);
        acc += wv.x * hv.x + wv.y * hv.y + wv.z * hv.z + wv.w * hv.w;
    }
    red[t] = acc;
    __syncthreads();
    #pragma unroll
    for (int s = 128; s; s >>= 1) {
        if (t < s) red[t] += red[t + s];
        __syncthreads();
    }
    if (t == 0) g_tag[b] = red[0] + bout[b];
}

// ---------------- K3b: log_softmax ----------------
__global__ void k3b(float* __restrict__ out) {
    __shared__ float st[NTAGS];
    __shared__ float m_s, l_s;
    const int t = threadIdx.x;
    float v = g_tag[t];
    st[t] = v;
    __syncthreads();
    if (t == 0) {
        float m = st[0];
        for (int i = 1; i < NTAGS; i++) m = fmaxf(m, st[i]);
        float s = 0.f;
        for (int i = 0; i < NTAGS; i++) s += expf(st[i] - m);
        m_s = m;
        l_s = logf(s);
    }
    __syncthreads();
    out[t] = v - m_s - l_s;
}

// ---------------- launch ----------------
extern "C" void kernel_launch(void* const* d_in, const int* in_sizes, int n_in,
                              void* d_out, int out_size) {
    const float* x    = (const float*)d_in[0];
    const float* Wih1 = (const float*)d_in[1];
    const float* Whh1 = (const float*)d_in[2];
    const float* bih1 = (const float*)d_in[3];
    const float* bhh1 = (const float*)d_in[4];
    const float* Wih2 = (const float*)d_in[5];
    const float* Whh2 = (const float*)d_in[6];
    const float* bih2 = (const float*)d_in[7];
    const float* bhh2 = (const float*)d_in[8];
    const float* Wout = (const float*)d_in[9];
    const float* bout = (const float*)d_in[10];

    cudaFuncSetAttribute(k2_recur, cudaFuncAttributeMaxDynamicSharedMemorySize, SMEM_BYTES);

    k0_quant<<<512, 256>>>(Whh1, Wih2, Whh2, bih2, bhh2);

    dim3 g1(G4 / 128, T_LEN / 128);
    k1_mma<<<g1, 256>>>(x, Wih1, bih1, bhh1);

    k2_recur<<<NCTA, NTHR, SMEM_BYTES>>>();

    k3a<<<NTAGS, 256>>>(Wout, bout);
    k3b<<<1, NTAGS>>>((float*)d_out);
}

// round 13
// speedup vs baseline: 1.1545x; 1.0491x over previous
#include <cuda_runtime.h>
#include <cuda_bf16.h>
#include <cstdint>

#define T_LEN 4096
#define E_DIM 1024
#define H_DIM 2048
#define G4    8192      // 4*H
#define NTAGS 128

#define NCTA   128
#define NTHR   512
#define NWARPS 16
#define W1_ROW 8192          // bytes: 4 gates * 2048 int8
#define W2_ROW 16384         // bytes: 4 gates * 4096 int8

// k2 SMEM layout:
//   shv  [0, 4096)                 staged h1q|h2q
//   sW1  [4096, +16*8192)          W1 rows, ALL warps
//   sW2  [135168, +11*8192)        W2 chunks 4..7 ([g][c-4], gate stride 2048), warps 0..10
#define SW1_OFF   4096
#define SW2_OFF   (SW1_OFF + 16*W1_ROW)          // 135168
#define SMEM_BYTES (SW2_OFF + 11*8192)           // 225280

// ---------------- static device buffers ----------------
__device__ __align__(16) signed char g_W1q[(size_t)H_DIM * W1_ROW];   // [j][g][k]
__device__ __align__(16) signed char g_W2q[(size_t)H_DIM * W2_ROW];   // [j][g][kk]
__device__ __align__(16) float g_s1[H_DIM * 4];
__device__ __align__(16) float g_s2[H_DIM * 4];
__device__ __align__(16) float g_P[(size_t)T_LEN * G4];
__device__ __align__(16) float g_b2[G4];
__device__ __align__(16) signed char g_h1q[2][H_DIM];
__device__ __align__(16) signed char g_h2q[2][H_DIM];
__device__ __align__(16) float g_h2f[H_DIM];
__device__ __align__(16) float g_tag[NTAGS];
__device__ unsigned g_count;             // barrier arrival counter (reset each launch in k0)

// ---------------- helpers ----------------
__device__ __forceinline__ unsigned ld_acq(unsigned* a) {
    unsigned v;
    asm volatile("ld.acquire.gpu.global.u32 %0, [%1];" : "=r"(v) : "l"(a) : "memory");
    return v;
}
__device__ __forceinline__ float sigf(float x) { return 1.0f / (1.0f + __expf(-x)); }
__device__ __forceinline__ float tanhfast(float x) {
    float e = __expf(2.0f * x);
    return 1.0f - __fdividef(2.0f, e + 1.0f);
}

__device__ __forceinline__ int dotq(int acc, int4 wv, int4 hv) {
    acc = __dp4a(wv.x, hv.x, acc);
    acc = __dp4a(wv.y, hv.y, acc);
    acc = __dp4a(wv.z, hv.z, acc);
    acc = __dp4a(wv.w, hv.w, acc);
    return acc;
}

// 4-gate int8 dot: wp = row base ([g][k] layout, gate stride GS bytes), hp = h vector
// NC chunks of 512 bytes; lane covers bytes [lane*16 + c*512, +16)
template<int NC, int GS>
__device__ __forceinline__ void dot4(const signed char* wp, const signed char* hp, int lane,
                                     int& a0, int& a1, int& a2, int& a3) {
    int off = lane * 16;
    #pragma unroll
    for (int c = 0; c < NC; c++, off += 512) {
        int4 hv = *(const int4*)(hp + off);
        int4 w0 = *(const int4*)(wp + off);
        int4 w1 = *(const int4*)(wp + GS + off);
        int4 w2 = *(const int4*)(wp + 2 * GS + off);
        int4 w3 = *(const int4*)(wp + 3 * GS + off);
        a0 = dotq(a0, w0, hv);
        a1 = dotq(a1, w1, hv);
        a2 = dotq(a2, w2, hv);
        a3 = dotq(a3, w3, hv);
    }
}

// ---------------- K0: quantize weights (fp32 -> int8 row-scaled) + misc init ----------------
__global__ void k0_quant(const float* __restrict__ Whh1,
                         const float* __restrict__ Wih2, const float* __restrict__ Whh2,
                         const float* __restrict__ bih2, const float* __restrict__ bhh2) {
    const int tid  = blockIdx.x * blockDim.x + threadIdx.x;
    const int nt   = gridDim.x * blockDim.x;
    const int gw   = tid >> 5;
    const int nw   = nt >> 5;
    const int lane = threadIdx.x & 31;

    // layer 1: 8192 gate-rows of 2048
    for (int r = gw; r < 8192; r += nw) {
        int j = r >> 2, g = r & 3;
        const float* src = Whh1 + (size_t)(g * H_DIM + j) * H_DIM;
        float m = 0.f;
        #pragma unroll 4
        for (int c = 0; c < 16; c++) {
            float4 v = *(const float4*)(src + c * 128 + lane * 4);
            m = fmaxf(m, fmaxf(fmaxf(fabsf(v.x), fabsf(v.y)), fmaxf(fabsf(v.z), fabsf(v.w))));
        }
        #pragma unroll
        for (int o = 16; o; o >>= 1) m = fmaxf(m, __shfl_xor_sync(0xffffffffu, m, o));
        float inv = (m > 0.f) ? 127.f / m : 0.f;
        signed char* dst = g_W1q + (size_t)j * W1_ROW + g * H_DIM;
        #pragma unroll 4
        for (int c = 0; c < 16; c++) {
            float4 v = *(const float4*)(src + c * 128 + lane * 4);
            int pk = (__float2int_rn(v.x * inv) & 255)
                   | ((__float2int_rn(v.y * inv) & 255) << 8)
                   | ((__float2int_rn(v.z * inv) & 255) << 16)
                   | ((__float2int_rn(v.w * inv) & 255) << 24);
            *(int*)(dst + c * 128 + lane * 4) = pk;
        }
        if (lane == 0) g_s1[j * 4 + g] = m / 16129.f;
    }

    // layer 2: 8192 gate-rows of 4096 (Wih2 | Whh2 concat)
    for (int r = gw; r < 8192; r += nw) {
        int j = r >> 2, g = r & 3;
        const float* sA = Wih2 + (size_t)(g * H_DIM + j) * H_DIM;
        const float* sB = Whh2 + (size_t)(g * H_DIM + j) * H_DIM;
        float m = 0.f;
        #pragma unroll 4
        for (int c = 0; c < 16; c++) {
            float4 v = *(const float4*)(sA + c * 128 + lane * 4);
            m = fmaxf(m, fmaxf(fmaxf(fabsf(v.x), fabsf(v.y)), fmaxf(fabsf(v.z), fabsf(v.w))));
        }
        #pragma unroll 4
        for (int c = 0; c < 16; c++) {
            float4 v = *(const float4*)(sB + c * 128 + lane * 4);
            m = fmaxf(m, fmaxf(fmaxf(fabsf(v.x), fabsf(v.y)), fmaxf(fabsf(v.z), fabsf(v.w))));
        }
        #pragma unroll
        for (int o = 16; o; o >>= 1) m = fmaxf(m, __shfl_xor_sync(0xffffffffu, m, o));
        float inv = (m > 0.f) ? 127.f / m : 0.f;
        signed char* dst = g_W2q + (size_t)j * W2_ROW + g * 2 * H_DIM;
        #pragma unroll 4
        for (int c = 0; c < 16; c++) {
            float4 v = *(const float4*)(sA + c * 128 + lane * 4);
            int pk = (__float2int_rn(v.x * inv) & 255)
                   | ((__float2int_rn(v.y * inv) & 255) << 8)
                   | ((__float2int_rn(v.z * inv) & 255) << 16)
                   | ((__float2int_rn(v.w * inv) & 255) << 24);
            *(int*)(dst + c * 128 + lane * 4) = pk;
        }
        #pragma unroll 4
        for (int c = 0; c < 16; c++) {
            float4 v = *(const float4*)(sB + c * 128 + lane * 4);
            int pk = (__float2int_rn(v.x * inv) & 255)
                   | ((__float2int_rn(v.y * inv) & 255) << 8)
                   | ((__float2int_rn(v.z * inv) & 255) << 16)
                   | ((__float2int_rn(v.w * inv) & 255) << 24);
            *(int*)(dst + H_DIM + c * 128 + lane * 4) = pk;
        }
        if (lane == 0) g_s2[j * 4 + g] = m / 16129.f;
    }

    for (int i = tid; i < G4; i += nt) g_b2[i] = bih2[i] + bhh2[i];
    for (int i = tid; i < H_DIM; i += nt) {
        g_h1q[0][i] = 0; g_h1q[1][i] = 0;
        g_h2q[0][i] = 0; g_h2q[1][i] = 0;
    }
    if (tid == 0) g_count = 0u;
}

// ---------------- K1: P = x @ W_ih1^T + bias via bf16 tensor-core MMA (unchanged) ----------------
__device__ __forceinline__ uint32_t pbf2(float lo, float hi) {
    __nv_bfloat162 h = __floats2bfloat162_rn(lo, hi);
    return *(uint32_t*)&h;
}
__device__ __forceinline__ void ldm_x4(uint32_t& r0, uint32_t& r1, uint32_t& r2, uint32_t& r3,
                                       uint32_t addr) {
    asm volatile("ldmatrix.sync.aligned.m8n8.x4.shared.b16 {%0,%1,%2,%3}, [%4];"
                 : "=r"(r0), "=r"(r1), "=r"(r2), "=r"(r3) : "r"(addr));
}
__device__ __forceinline__ void mma_bf16(float* d, const uint32_t* a, uint32_t b0, uint32_t b1) {
    asm volatile("mma.sync.aligned.m16n8k16.row.col.f32.bf16.bf16.f32 "
                 "{%0,%1,%2,%3}, {%4,%5,%6,%7}, {%8,%9}, {%0,%1,%2,%3};"
                 : "+f"(d[0]), "+f"(d[1]), "+f"(d[2]), "+f"(d[3])
                 : "r"(a[0]), "r"(a[1]), "r"(a[2]), "r"(a[3]), "r"(b0), "r"(b1));
}

#define K1_STRIDE 40   // bf16 elements per smem row (32 data + 8 pad = 80B, conflict-free)

__global__ void __launch_bounds__(256) k1_mma(const float* __restrict__ X,
                                              const float* __restrict__ W,
                                              const float* __restrict__ b1,
                                              const float* __restrict__ b2) {
    __shared__ __align__(16) __nv_bfloat16 sA[128 * K1_STRIDE];
    __shared__ __align__(16) __nv_bfloat16 sB[128 * K1_STRIDE];

    const int t    = threadIdx.x;
    const int warp = t >> 5;
    const int lane = t & 31;
    const int wm   = warp >> 2;
    const int wn   = warp & 3;
    const int m0   = blockIdx.y * 128;
    const int n0   = blockIdx.x * 128;

    const int lr = t >> 1;
    const int lc = (t & 1) * 16;

    float acc[4][4][4];
    #pragma unroll
    for (int i = 0; i < 4; i++)
        #pragma unroll
        for (int j = 0; j < 4; j++)
            #pragma unroll
            for (int q = 0; q < 4; q++) acc[i][j][q] = 0.f;

    uint32_t sA_base = (uint32_t)__cvta_generic_to_shared(sA);
    uint32_t sB_base = (uint32_t)__cvta_generic_to_shared(sB);

    for (int kt = 0; kt < E_DIM; kt += 32) {
        const float4* xs = (const float4*)(X + (size_t)(m0 + lr) * E_DIM + kt + lc);
        const float4* ws = (const float4*)(W + (size_t)(n0 + lr) * E_DIM + kt + lc);
        float4 x0 = xs[0], x1 = xs[1], x2 = xs[2], x3 = xs[3];
        float4 w0 = ws[0], w1 = ws[1], w2 = ws[2], w3 = ws[3];
        __syncthreads();
        {
            uint4 pa, pb;
            pa.x = pbf2(x0.x, x0.y); pa.y = pbf2(x0.z, x0.w);
            pa.z = pbf2(x1.x, x1.y); pa.w = pbf2(x1.z, x1.w);
            pb.x = pbf2(x2.x, x2.y); pb.y = pbf2(x2.z, x2.w);
            pb.z = pbf2(x3.x, x3.y); pb.w = pbf2(x3.z, x3.w);
            *(uint4*)(sA + lr * K1_STRIDE + lc)     = pa;
            *(uint4*)(sA + lr * K1_STRIDE + lc + 8) = pb;
            pa.x = pbf2(w0.x, w0.y); pa.y = pbf2(w0.z, w0.w);
            pa.z = pbf2(w1.x, w1.y); pa.w = pbf2(w1.z, w1.w);
            pb.x = pbf2(w2.x, w2.y); pb.y = pbf2(w2.z, w2.w);
            pb.z = pbf2(w3.x, w3.y); pb.w = pbf2(w3.z, w3.w);
            *(uint4*)(sB + lr * K1_STRIDE + lc)     = pa;
            *(uint4*)(sB + lr * K1_STRIDE + lc + 8) = pb;
        }
        __syncthreads();

        #pragma unroll
        for (int ks = 0; ks < 2; ks++) {
            uint32_t af[4][4];
            #pragma unroll
            for (int mt = 0; mt < 4; mt++) {
                int row = wm * 64 + mt * 16 + (lane & 15);
                uint32_t addr = sA_base + (uint32_t)(row * K1_STRIDE + ks * 16 + (lane >> 4) * 8) * 2u;
                ldm_x4(af[mt][0], af[mt][1], af[mt][2], af[mt][3], addr);
            }
            uint32_t bf[4][2];
            #pragma unroll
            for (int bt = 0; bt < 2; bt++) {
                int row = wn * 32 + bt * 16 + (lane & 15);
                uint32_t addr = sB_base + (uint32_t)(row * K1_STRIDE + ks * 16 + (lane >> 4) * 8) * 2u;
                uint32_t q0, q1, q2, q3;
                ldm_x4(q0, q1, q2, q3, addr);
                bf[bt * 2 + 0][0] = q0; bf[bt * 2 + 0][1] = q2;
                bf[bt * 2 + 1][0] = q1; bf[bt * 2 + 1][1] = q3;
            }
            #pragma unroll
            for (int mt = 0; mt < 4; mt++)
                #pragma unroll
                for (int nt = 0; nt < 4; nt++)
                    mma_bf16(acc[mt][nt], af[mt], bf[nt][0], bf[nt][1]);
        }
    }

    #pragma unroll
    for (int nt = 0; nt < 4; nt++) {
        int col = n0 + wn * 32 + nt * 8 + (lane & 3) * 2;
        float bc0 = __ldg(&b1[col])     + __ldg(&b2[col]);
        float bc1 = __ldg(&b1[col + 1]) + __ldg(&b2[col + 1]);
        #pragma unroll
        for (int mt = 0; mt < 4; mt++) {
            int row = m0 + wm * 64 + mt * 16 + (lane >> 2);
            float2 v0 = make_float2(acc[mt][nt][0] + bc0, acc[mt][nt][1] + bc1);
            float2 v1 = make_float2(acc[mt][nt][2] + bc0, acc[mt][nt][3] + bc1);
            __stcs((float2*)(g_P + (size_t)row * G4 + col), v0);
            __stcs((float2*)(g_P + (size_t)(row + 8) * G4 + col), v1);
        }
    }
}

// ---------------- K2: persistent int8 recurrent kernel, 64-reg W2 cache ----------------
__global__ void __launch_bounds__(NTHR, 1) k2_recur() {
    extern __shared__ __align__(16) signed char smem[];
    signed char* shv = smem;                         // 4096: h1q(2048) | h2q(2048)

    const int tid  = threadIdx.x;
    const int warp = tid >> 5;
    const int lane = tid & 31;
    const int w    = blockIdx.x * NWARPS + warp;     // owned h-row, both layers

    const signed char* wg1 = g_W1q + (size_t)w * W1_ROW;
    const signed char* wg2 = g_W2q + (size_t)w * W2_ROW;

    // pin W1 rows: ALL warps
    {
        const int4* src = (const int4*)wg1;
        int4* dst = (int4*)(smem + SW1_OFF + (size_t)warp * W1_ROW);
        #pragma unroll
        for (int i = 0; i < 16; i++) dst[lane + i * 32] = src[lane + i * 32];
    }
    // pin W2 chunks 4..7 for warps 0..10 ([g][c-4] layout, gate stride 2048)
    if (warp < 11) {
        signed char* dst = smem + SW2_OFF + (size_t)warp * 8192;
        #pragma unroll
        for (int g = 0; g < 4; g++)
            #pragma unroll
            for (int c = 4; c < 8; c++)
                *(int4*)(dst + g * 2048 + (c - 4) * 512 + lane * 16) =
                    *(const int4*)(wg2 + g * 4096 + c * 512 + lane * 16);
    }
    // ALL warps: W2 chunks 0..3 (== Wih2 half, input h1q) permanently in registers.
    // rc[c][g], 16 int4 = 64 regs/thread.
    int4 rc[4][4];
    #pragma unroll
    for (int c = 0; c < 4; c++)
        #pragma unroll
        for (int g = 0; g < 4; g++)
            rc[c][g] = *(const int4*)(wg2 + g * 4096 + c * 512 + lane * 16);

    const float4 fs1 = *(const float4*)(g_s1 + w * 4);
    const float4 fs2 = *(const float4*)(g_s2 + w * 4);
    const float bi = g_b2[w], bf = g_b2[w + H_DIM], bg = g_b2[w + 2*H_DIM], bo = g_b2[w + 3*H_DIM];

    float c1 = 0.f, c2 = 0.f;

    for (int p = 0; p <= T_LEN; p++) {
        // prefetch this step's P early (independent of the staged h)
        float p0 = 0.f, p1 = 0.f, p2 = 0.f, p3 = 0.f;
        if (lane == 0 && p < T_LEN) {
            size_t pb = (size_t)p * G4 + w;
            p0 = __ldcs(&g_P[pb]);
            p1 = __ldcs(&g_P[pb + H_DIM]);
            p2 = __ldcs(&g_P[pb + 2*H_DIM]);
            p3 = __ldcs(&g_P[pb + 3*H_DIM]);
        }

        // stage h vectors: shv[0:2048]=h1q_{p-1}, shv[2048:4096]=h2q_{p-2}
        {
            const int2* s1 = (const int2*)g_h1q[p & 1];
            const int2* s2 = (const int2*)g_h2q[(p + 1) & 1];
            if (tid < 256) ((int2*)shv)[tid] = __ldcg(s1 + tid);
            else           ((int2*)shv)[tid] = __ldcg(s2 + (tid - 256));
        }
        __syncthreads();

        // -------- layer 1, step t = p (always SMEM) --------
        if (p < T_LEN) {
            int a0 = 0, a1 = 0, a2 = 0, a3 = 0;
            dot4<4, H_DIM>(smem + SW1_OFF + (size_t)warp * W1_ROW, shv, lane, a0, a1, a2, a3);
            a0 = __reduce_add_sync(0xffffffffu, a0);
            a1 = __reduce_add_sync(0xffffffffu, a1);
            a2 = __reduce_add_sync(0xffffffffu, a2);
            a3 = __reduce_add_sync(0xffffffffu, a3);
            if (lane == 0) {
                float gi  = (float)a0 * fs1.x + p0;
                float gf_ = (float)a1 * fs1.y + p1;
                float gg  = (float)a2 * fs1.z + p2;
                float go_ = (float)a3 * fs1.w + p3;
                c1 = sigf(gf_) * c1 + sigf(gi) * tanhfast(gg);
                float h = sigf(go_) * tanhfast(c1);
                g_h1q[(p + 1) & 1][w] = (signed char)__float2int_rn(h * 127.f);
            }
        }

        // -------- layer 2, step t = p-1 (input [h1q_{p-1} ; h2q_{p-2}] = shv) --------
        if (p >= 1) {
            int a0 = 0, a1 = 0, a2 = 0, a3 = 0;
            const int off0 = lane * 16;
            // chunks 0..3 (Wih2 · h1) from registers
            #pragma unroll
            for (int c = 0; c < 4; c++) {
                int4 hv = *(const int4*)(shv + c * 512 + off0);
                a0 = dotq(a0, rc[c][0], hv);
                a1 = dotq(a1, rc[c][1], hv);
                a2 = dotq(a2, rc[c][2], hv);
                a3 = dotq(a3, rc[c][3], hv);
            }
            // chunks 4..7 (Whh2 · h2): SMEM for warps 0..10, gmem for 11..15
            if (warp < 11)
                dot4<4, 2048>(smem + SW2_OFF + (size_t)warp * 8192, shv + 2048, lane, a0, a1, a2, a3);
            else
                dot4<4, 2*H_DIM>(wg2 + 2048, shv + 2048, lane, a0, a1, a2, a3);
            a0 = __reduce_add_sync(0xffffffffu, a0);
            a1 = __reduce_add_sync(0xffffffffu, a1);
            a2 = __reduce_add_sync(0xffffffffu, a2);
            a3 = __reduce_add_sync(0xffffffffu, a3);
            if (lane == 0) {
                float gi  = (float)a0 * fs2.x + bi;
                float gf_ = (float)a1 * fs2.y + bf;
                float gg  = (float)a2 * fs2.z + bg;
                float go_ = (float)a3 * fs2.w + bo;
                c2 = sigf(gf_) * c2 + sigf(gi) * tanhfast(gg);
                float h = sigf(go_) * tanhfast(c2);
                g_h2q[p & 1][w] = (signed char)__float2int_rn(h * 127.f);
                if (p == T_LEN) g_h2f[w] = h;
            }
        }

        // -------- grid barrier: fence + atomicAdd arrive, single-word acquire poll --------
        __syncthreads();
        if (tid == 0) {
            __threadfence();                         // release: publish h-state stores
            atomicAdd(&g_count, 1u);
            unsigned tgt = (unsigned)(p + 1) * (unsigned)NCTA;
            while (ld_acq(&g_count) < tgt) { }
        }
        __syncthreads();
    }
}

// ---------------- K3a: tag_space = h2 @ W_out^T + b_out (one block per tag) ----------------
__global__ void k3a(const float* __restrict__ Wout, const float* __restrict__ bout) {
    __shared__ float red[256];
    const int b = blockIdx.x, t = threadIdx.x;
    float acc = 0.f;
    #pragma unroll
    for (int c = 0; c < 2; c++) {
        float4 wv = *(const float4*)(Wout + (size_t)b * H_DIM + c * 1024 + t * 4);
        float4 hv = *(const float4*)(g_h2f + c * 1024 + t * 4);
        acc += wv.x * hv.x + wv.y * hv.y + wv.z * hv.z + wv.w * hv.w;
    }
    red[t] = acc;
    __syncthreads();
    #pragma unroll
    for (int s = 128; s; s >>= 1) {
        if (t < s) red[t] += red[t + s];
        __syncthreads();
    }
    if (t == 0) g_tag[b] = red[0] + bout[b];
}

// ---------------- K3b: log_softmax ----------------
__global__ void k3b(float* __restrict__ out) {
    __shared__ float st[NTAGS];
    __shared__ float m_s, l_s;
    const int t = threadIdx.x;
    float v = g_tag[t];
    st[t] = v;
    __syncthreads();
    if (t == 0) {
        float m = st[0];
        for (int i = 1; i < NTAGS; i++) m = fmaxf(m, st[i]);
        float s = 0.f;
        for (int i = 0; i < NTAGS; i++) s += expf(st[i] - m);
        m_s = m;
        l_s = logf(s);
    }
    __syncthreads();
    out[t] = v - m_s - l_s;
}

// ---------------- launch ----------------
extern "C" void kernel_launch(void* const* d_in, const int* in_sizes, int n_in,
                              void* d_out, int out_size) {
    const float* x    = (const float*)d_in[0];
    const float* Wih1 = (const float*)d_in[1];
    const float* Whh1 = (const float*)d_in[2];
    const float* bih1 = (const float*)d_in[3];
    const float* bhh1 = (const float*)d_in[4];
    const float* Wih2 = (const float*)d_in[5];
    const float* Whh2 = (const float*)d_in[6];
    const float* bih2 = (const float*)d_in[7];
    const float* bhh2 = (const float*)d_in[8];
    const float* Wout = (const float*)d_in[9];
    const float* bout = (const float*)d_in[10];

    cudaFuncSetAttribute(k2_recur, cudaFuncAttributeMaxDynamicSharedMemorySize, SMEM_BYTES);

    k0_quant<<<512, 256>>>(Whh1, Wih2, Whh2, bih2, bhh2);

    dim3 g1(G4 / 128, T_LEN / 128);
    k1_mma<<<g1, 256>>>(x, Wih1, bih1, bhh1);

    k2_recur<<<NCTA, NTHR, SMEM_BYTES>>>();

    k3a<<<NTAGS, 256>>>(Wout, bout);
    k3b<<<1, NTAGS>>>((float*)d_out);
}

// round 14
// speedup vs baseline: 1.2018x; 1.0409x over previous
#include <cuda_runtime.h>
#include <cuda_bf16.h>
#include <cstdint>

#define T_LEN 4096
#define E_DIM 1024
#define H_DIM 2048
#define G4    8192      // 4*H
#define NTAGS 128

#define NCTA   128
#define NTHR   512
#define NWARPS 16
#define W1_ROW 8192          // bytes: 4 gates * 2048 int8
#define W2_ROW 16384         // bytes: 4 gates * 4096 int8

// k2 SMEM layout:
//   shv  [0, 4096)                 staged h1q|h2q
//   sW1  [4096, +16*8192)          W1 rows, ALL warps
//   sW2  [135168, +11*8192)        W2 chunks 4..7 ([g][c-4], gate stride 2048), warps 0..10
#define SW1_OFF   4096
#define SW2_OFF   (SW1_OFF + 16*W1_ROW)          // 135168
#define SMEM_BYTES (SW2_OFF + 11*8192)           // 225280

// ---------------- static device buffers ----------------
__device__ __align__(16) signed char g_W1q[(size_t)H_DIM * W1_ROW];   // [j][g][k]
__device__ __align__(16) signed char g_W2q[(size_t)H_DIM * W2_ROW];   // [j][g][kk]
__device__ __align__(16) float g_s1[H_DIM * 4];
__device__ __align__(16) float g_s2[H_DIM * 4];
__device__ __align__(16) float g_P[(size_t)T_LEN * G4];
__device__ __align__(16) float g_b2[G4];
__device__ __align__(16) signed char g_h1q[2][H_DIM];
__device__ __align__(16) signed char g_h2q[2][H_DIM];
__device__ __align__(16) float g_h2f[H_DIM];
__device__ __align__(16) float g_tag[NTAGS];
__device__ unsigned g_count;             // barrier arrival counter (reset each launch in k0)

// ---------------- helpers ----------------
__device__ __forceinline__ unsigned ld_acq(unsigned* a) {
    unsigned v;
    asm volatile("ld.acquire.gpu.global.u32 %0, [%1];" : "=r"(v) : "l"(a) : "memory");
    return v;
}
__device__ __forceinline__ float sigf(float x) { return 1.0f / (1.0f + __expf(-x)); }
__device__ __forceinline__ float tanhfast(float x) {
    float e = __expf(2.0f * x);
    return 1.0f - __fdividef(2.0f, e + 1.0f);
}

__device__ __forceinline__ int dotq(int acc, int4 wv, int4 hv) {
    acc = __dp4a(wv.x, hv.x, acc);
    acc = __dp4a(wv.y, hv.y, acc);
    acc = __dp4a(wv.z, hv.z, acc);
    acc = __dp4a(wv.w, hv.w, acc);
    return acc;
}

// 4-gate int8 dot: wp = row base ([g][k] layout, gate stride GS bytes), hp = h vector
template<int NC, int GS>
__device__ __forceinline__ void dot4(const signed char* wp, const signed char* hp, int lane,
                                     int& a0, int& a1, int& a2, int& a3) {
    int off = lane * 16;
    #pragma unroll
    for (int c = 0; c < NC; c++, off += 512) {
        int4 hv = *(const int4*)(hp + off);
        int4 w0 = *(const int4*)(wp + off);
        int4 w1 = *(const int4*)(wp + GS + off);
        int4 w2 = *(const int4*)(wp + 2 * GS + off);
        int4 w3 = *(const int4*)(wp + 3 * GS + off);
        a0 = dotq(a0, w0, hv);
        a1 = dotq(a1, w1, hv);
        a2 = dotq(a2, w2, hv);
        a3 = dotq(a3, w3, hv);
    }
}

// ---------------- K0: quantize weights (fp32 -> int8 row-scaled) + misc init ----------------
__global__ void k0_quant(const float* __restrict__ Whh1,
                         const float* __restrict__ Wih2, const float* __restrict__ Whh2,
                         const float* __restrict__ bih2, const float* __restrict__ bhh2) {
    const int tid  = blockIdx.x * blockDim.x + threadIdx.x;
    const int nt   = gridDim.x * blockDim.x;
    const int gw   = tid >> 5;
    const int nw   = nt >> 5;
    const int lane = threadIdx.x & 31;

    for (int r = gw; r < 8192; r += nw) {
        int j = r >> 2, g = r & 3;
        const float* src = Whh1 + (size_t)(g * H_DIM + j) * H_DIM;
        float m = 0.f;
        #pragma unroll 4
        for (int c = 0; c < 16; c++) {
            float4 v = *(const float4*)(src + c * 128 + lane * 4);
            m = fmaxf(m, fmaxf(fmaxf(fabsf(v.x), fabsf(v.y)), fmaxf(fabsf(v.z), fabsf(v.w))));
        }
        #pragma unroll
        for (int o = 16; o; o >>= 1) m = fmaxf(m, __shfl_xor_sync(0xffffffffu, m, o));
        float inv = (m > 0.f) ? 127.f / m : 0.f;
        signed char* dst = g_W1q + (size_t)j * W1_ROW + g * H_DIM;
        #pragma unroll 4
        for (int c = 0; c < 16; c++) {
            float4 v = *(const float4*)(src + c * 128 + lane * 4);
            int pk = (__float2int_rn(v.x * inv) & 255)
                   | ((__float2int_rn(v.y * inv) & 255) << 8)
                   | ((__float2int_rn(v.z * inv) & 255) << 16)
                   | ((__float2int_rn(v.w * inv) & 255) << 24);
            *(int*)(dst + c * 128 + lane * 4) = pk;
        }
        if (lane == 0) g_s1[j * 4 + g] = m / 16129.f;
    }

    for (int r = gw; r < 8192; r += nw) {
        int j = r >> 2, g = r & 3;
        const float* sA = Wih2 + (size_t)(g * H_DIM + j) * H_DIM;
        const float* sB = Whh2 + (size_t)(g * H_DIM + j) * H_DIM;
        float m = 0.f;
        #pragma unroll 4
        for (int c = 0; c < 16; c++) {
            float4 v = *(const float4*)(sA + c * 128 + lane * 4);
            m = fmaxf(m, fmaxf(fmaxf(fabsf(v.x), fabsf(v.y)), fmaxf(fabsf(v.z), fabsf(v.w))));
        }
        #pragma unroll 4
        for (int c = 0; c < 16; c++) {
            float4 v = *(const float4*)(sB + c * 128 + lane * 4);
            m = fmaxf(m, fmaxf(fmaxf(fabsf(v.x), fabsf(v.y)), fmaxf(fabsf(v.z), fabsf(v.w))));
        }
        #pragma unroll
        for (int o = 16; o; o >>= 1) m = fmaxf(m, __shfl_xor_sync(0xffffffffu, m, o));
        float inv = (m > 0.f) ? 127.f / m : 0.f;
        signed char* dst = g_W2q + (size_t)j * W2_ROW + g * 2 * H_DIM;
        #pragma unroll 4
        for (int c = 0; c < 16; c++) {
            float4 v = *(const float4*)(sA + c * 128 + lane * 4);
            int pk = (__float2int_rn(v.x * inv) & 255)
                   | ((__float2int_rn(v.y * inv) & 255) << 8)
                   | ((__float2int_rn(v.z * inv) & 255) << 16)
                   | ((__float2int_rn(v.w * inv) & 255) << 24);
            *(int*)(dst + c * 128 + lane * 4) = pk;
        }
        #pragma unroll 4
        for (int c = 0; c < 16; c++) {
            float4 v = *(const float4*)(sB + c * 128 + lane * 4);
            int pk = (__float2int_rn(v.x * inv) & 255)
                   | ((__float2int_rn(v.y * inv) & 255) << 8)
                   | ((__float2int_rn(v.z * inv) & 255) << 16)
                   | ((__float2int_rn(v.w * inv) & 255) << 24);
            *(int*)(dst + H_DIM + c * 128 + lane * 4) = pk;
        }
        if (lane == 0) g_s2[j * 4 + g] = m / 16129.f;
    }

    for (int i = tid; i < G4; i += nt) g_b2[i] = bih2[i] + bhh2[i];
    for (int i = tid; i < H_DIM; i += nt) {
        g_h1q[0][i] = 0; g_h1q[1][i] = 0;
        g_h2q[0][i] = 0; g_h2q[1][i] = 0;
    }
    if (tid == 0) g_count = 0u;
}

// ---------------- K1: bf16 tensor-core GEMM, register-pipelined global loads ----------------
__device__ __forceinline__ uint32_t pbf2(float lo, float hi) {
    __nv_bfloat162 h = __floats2bfloat162_rn(lo, hi);
    return *(uint32_t*)&h;
}
__device__ __forceinline__ void ldm_x4(uint32_t& r0, uint32_t& r1, uint32_t& r2, uint32_t& r3,
                                       uint32_t addr) {
    asm volatile("ldmatrix.sync.aligned.m8n8.x4.shared.b16 {%0,%1,%2,%3}, [%4];"
                 : "=r"(r0), "=r"(r1), "=r"(r2), "=r"(r3) : "r"(addr));
}
__device__ __forceinline__ void mma_bf16(float* d, const uint32_t* a, uint32_t b0, uint32_t b1) {
    asm volatile("mma.sync.aligned.m16n8k16.row.col.f32.bf16.bf16.f32 "
                 "{%0,%1,%2,%3}, {%4,%5,%6,%7}, {%8,%9}, {%0,%1,%2,%3};"
                 : "+f"(d[0]), "+f"(d[1]), "+f"(d[2]), "+f"(d[3])
                 : "r"(a[0]), "r"(a[1]), "r"(a[2]), "r"(a[3]), "r"(b0), "r"(b1));
}

#define K1_STRIDE 40   // bf16 elements per smem row (32 data + 8 pad = 80B, conflict-free)

__global__ void __launch_bounds__(256) k1_mma(const float* __restrict__ X,
                                              const float* __restrict__ W,
                                              const float* __restrict__ b1,
                                              const float* __restrict__ b2) {
    __shared__ __align__(16) __nv_bfloat16 sA[128 * K1_STRIDE];
    __shared__ __align__(16) __nv_bfloat16 sB[128 * K1_STRIDE];

    const int t    = threadIdx.x;
    const int warp = t >> 5;
    const int lane = t & 31;
    const int wm   = warp >> 2;
    const int wn   = warp & 3;
    const int m0   = blockIdx.y * 128;
    const int n0   = blockIdx.x * 128;

    const int lr = t >> 1;
    const int lc = (t & 1) * 16;

    float acc[4][4][4];
    #pragma unroll
    for (int i = 0; i < 4; i++)
        #pragma unroll
        for (int j = 0; j < 4; j++)
            #pragma unroll
            for (int q = 0; q < 4; q++) acc[i][j][q] = 0.f;

    uint32_t sA_base = (uint32_t)__cvta_generic_to_shared(sA);
    uint32_t sB_base = (uint32_t)__cvta_generic_to_shared(sB);

    const float* xrow = X + (size_t)(m0 + lr) * E_DIM + lc;
    const float* wrow = W + (size_t)(n0 + lr) * E_DIM + lc;

    // preload k-tile 0
    float4 x0 = ((const float4*)xrow)[0], x1 = ((const float4*)xrow)[1];
    float4 x2 = ((const float4*)xrow)[2], x3 = ((const float4*)xrow)[3];
    float4 w0 = ((const float4*)wrow)[0], w1 = ((const float4*)wrow)[1];
    float4 w2 = ((const float4*)wrow)[2], w3 = ((const float4*)wrow)[3];

    for (int kt = 0; kt < E_DIM; kt += 32) {
        __syncthreads();
        {
            uint4 pa, pb;
            pa.x = pbf2(x0.x, x0.y); pa.y = pbf2(x0.z, x0.w);
            pa.z = pbf2(x1.x, x1.y); pa.w = pbf2(x1.z, x1.w);
            pb.x = pbf2(x2.x, x2.y); pb.y = pbf2(x2.z, x2.w);
            pb.z = pbf2(x3.x, x3.y); pb.w = pbf2(x3.z, x3.w);
            *(uint4*)(sA + lr * K1_STRIDE + lc)     = pa;
            *(uint4*)(sA + lr * K1_STRIDE + lc + 8) = pb;
            pa.x = pbf2(w0.x, w0.y); pa.y = pbf2(w0.z, w0.w);
            pa.z = pbf2(w1.x, w1.y); pa.w = pbf2(w1.z, w1.w);
            pb.x = pbf2(w2.x, w2.y); pb.y = pbf2(w2.z, w2.w);
            pb.z = pbf2(w3.x, w3.y); pb.w = pbf2(w3.z, w3.w);
            *(uint4*)(sB + lr * K1_STRIDE + lc)     = pa;
            *(uint4*)(sB + lr * K1_STRIDE + lc + 8) = pb;
        }
        __syncthreads();

        // issue next tile's global loads early: latency hides behind the mma section
        if (kt + 32 < E_DIM) {
            const float4* xs = (const float4*)(xrow + kt + 32);
            const float4* ws = (const float4*)(wrow + kt + 32);
            x0 = xs[0]; x1 = xs[1]; x2 = xs[2]; x3 = xs[3];
            w0 = ws[0]; w1 = ws[1]; w2 = ws[2]; w3 = ws[3];
        }

        #pragma unroll
        for (int ks = 0; ks < 2; ks++) {
            uint32_t af[4][4];
            #pragma unroll
            for (int mt = 0; mt < 4; mt++) {
                int row = wm * 64 + mt * 16 + (lane & 15);
                uint32_t addr = sA_base + (uint32_t)(row * K1_STRIDE + ks * 16 + (lane >> 4) * 8) * 2u;
                ldm_x4(af[mt][0], af[mt][1], af[mt][2], af[mt][3], addr);
            }
            uint32_t bf[4][2];
            #pragma unroll
            for (int bt = 0; bt < 2; bt++) {
                int row = wn * 32 + bt * 16 + (lane & 15);
                uint32_t addr = sB_base + (uint32_t)(row * K1_STRIDE + ks * 16 + (lane >> 4) * 8) * 2u;
                uint32_t q0, q1, q2, q3;
                ldm_x4(q0, q1, q2, q3, addr);
                bf[bt * 2 + 0][0] = q0; bf[bt * 2 + 0][1] = q2;
                bf[bt * 2 + 1][0] = q1; bf[bt * 2 + 1][1] = q3;
            }
            #pragma unroll
            for (int mt = 0; mt < 4; mt++)
                #pragma unroll
                for (int nt = 0; nt < 4; nt++)
                    mma_bf16(acc[mt][nt], af[mt], bf[nt][0], bf[nt][1]);
        }
    }

    #pragma unroll
    for (int nt = 0; nt < 4; nt++) {
        int col = n0 + wn * 32 + nt * 8 + (lane & 3) * 2;
        float bc0 = __ldg(&b1[col])     + __ldg(&b2[col]);
        float bc1 = __ldg(&b1[col + 1]) + __ldg(&b2[col + 1]);
        #pragma unroll
        for (int mt = 0; mt < 4; mt++) {
            int row = m0 + wm * 64 + mt * 16 + (lane >> 2);
            float2 v0 = make_float2(acc[mt][nt][0] + bc0, acc[mt][nt][1] + bc1);
            float2 v1 = make_float2(acc[mt][nt][2] + bc0, acc[mt][nt][3] + bc1);
            __stcs((float2*)(g_P + (size_t)row * G4 + col), v0);
            __stcs((float2*)(g_P + (size_t)(row + 8) * G4 + col), v1);
        }
    }
}

// ---------------- K2: persistent int8 recurrent kernel, fused h1 loads ----------------
__global__ void __launch_bounds__(NTHR, 1) k2_recur() {
    extern __shared__ __align__(16) signed char smem[];
    signed char* shv = smem;                         // 4096: h1q(2048) | h2q(2048)

    const int tid  = threadIdx.x;
    const int warp = tid >> 5;
    const int lane = tid & 31;
    const int w    = blockIdx.x * NWARPS + warp;     // owned h-row, both layers

    const signed char* wg1 = g_W1q + (size_t)w * W1_ROW;
    const signed char* wg2 = g_W2q + (size_t)w * W2_ROW;
    const signed char* sw1 = smem + SW1_OFF + (size_t)warp * W1_ROW;

    // pin W1 rows: ALL warps
    {
        const int4* src = (const int4*)wg1;
        int4* dst = (int4*)sw1;
        #pragma unroll
        for (int i = 0; i < 16; i++) dst[lane + i * 32] = src[lane + i * 32];
    }
    // pin W2 chunks 4..7 for warps 0..10 ([g][c-4] layout, gate stride 2048)
    if (warp < 11) {
        signed char* dst = smem + SW2_OFF + (size_t)warp * 8192;
        #pragma unroll
        for (int g = 0; g < 4; g++)
            #pragma unroll
            for (int c = 4; c < 8; c++)
                *(int4*)(dst + g * 2048 + (c - 4) * 512 + lane * 16) =
                    *(const int4*)(wg2 + g * 4096 + c * 512 + lane * 16);
    }
    // ALL warps: W2 chunks 0..3 (Wih2 half, input h1q) permanently in registers.
    int4 rc[4][4];
    #pragma unroll
    for (int c = 0; c < 4; c++)
        #pragma unroll
        for (int g = 0; g < 4; g++)
            rc[c][g] = *(const int4*)(wg2 + g * 4096 + c * 512 + lane * 16);

    const float4 fs1 = *(const float4*)(g_s1 + w * 4);
    const float4 fs2 = *(const float4*)(g_s2 + w * 4);
    const float bi = g_b2[w], bf = g_b2[w + H_DIM], bg = g_b2[w + 2*H_DIM], bo = g_b2[w + 3*H_DIM];

    float c1 = 0.f, c2 = 0.f;

    for (int p = 0; p <= T_LEN; p++) {
        // prefetch this step's P early (independent of the staged h)
        float p0 = 0.f, p1 = 0.f, p2 = 0.f, p3 = 0.f;
        if (lane == 0 && p < T_LEN) {
            size_t pb = (size_t)p * G4 + w;
            p0 = __ldcs(&g_P[pb]);
            p1 = __ldcs(&g_P[pb + H_DIM]);
            p2 = __ldcs(&g_P[pb + 2*H_DIM]);
            p3 = __ldcs(&g_P[pb + 3*H_DIM]);
        }

        // stage h vectors: shv[0:2048]=h1q_{p-1}, shv[2048:4096]=h2q_{p-2}
        {
            const int2* s1 = (const int2*)g_h1q[p & 1];
            const int2* s2 = (const int2*)g_h2q[(p + 1) & 1];
            if (tid < 256) ((int2*)shv)[tid] = __ldcg(s1 + tid);
            else           ((int2*)shv)[tid] = __ldcg(s2 + (tid - 256));
        }
        __syncthreads();

        const int off0 = lane * 16;
        int a0 = 0, a1 = 0, a2 = 0, a3 = 0;   // layer 1 gates
        int b0 = 0, b1 = 0, b2 = 0, b3 = 0;   // layer 2 gates

        if (p >= 1 && p < T_LEN) {
            // fused: each h1 chunk feeds BOTH W1 (smem) and W2 chunks 0..3 (regs)
            #pragma unroll
            for (int c = 0; c < 4; c++) {
                int4 hv = *(const int4*)(shv + c * 512 + off0);
                int4 u0 = *(const int4*)(sw1 + c * 512 + off0);
                int4 u1 = *(const int4*)(sw1 + H_DIM + c * 512 + off0);
                int4 u2 = *(const int4*)(sw1 + 2 * H_DIM + c * 512 + off0);
                int4 u3 = *(const int4*)(sw1 + 3 * H_DIM + c * 512 + off0);
                a0 = dotq(a0, u0, hv);
                a1 = dotq(a1, u1, hv);
                a2 = dotq(a2, u2, hv);
                a3 = dotq(a3, u3, hv);
                b0 = dotq(b0, rc[c][0], hv);
                b1 = dotq(b1, rc[c][1], hv);
                b2 = dotq(b2, rc[c][2], hv);
                b3 = dotq(b3, rc[c][3], hv);
            }
        } else if (p < T_LEN) {           // p == 0: layer 1 only
            dot4<4, H_DIM>(sw1, shv, lane, a0, a1, a2, a3);
        } else {                          // p == T_LEN: layer 2 reg part only
            #pragma unroll
            for (int c = 0; c < 4; c++) {
                int4 hv = *(const int4*)(shv + c * 512 + off0);
                b0 = dotq(b0, rc[c][0], hv);
                b1 = dotq(b1, rc[c][1], hv);
                b2 = dotq(b2, rc[c][2], hv);
                b3 = dotq(b3, rc[c][3], hv);
            }
        }

        // layer 2 chunks 4..7 (Whh2 · h2): SMEM warps 0..10, gmem 11..15
        if (p >= 1) {
            if (warp < 11)
                dot4<4, 2048>(smem + SW2_OFF + (size_t)warp * 8192, shv + 2048, lane, b0, b1, b2, b3);
            else
                dot4<4, 2*H_DIM>(wg2 + 2048, shv + 2048, lane, b0, b1, b2, b3);
        }

        // reductions + epilogues
        if (p < T_LEN) {
            a0 = __reduce_add_sync(0xffffffffu, a0);
            a1 = __reduce_add_sync(0xffffffffu, a1);
            a2 = __reduce_add_sync(0xffffffffu, a2);
            a3 = __reduce_add_sync(0xffffffffu, a3);
        }
        if (p >= 1) {
            b0 = __reduce_add_sync(0xffffffffu, b0);
            b1 = __reduce_add_sync(0xffffffffu, b1);
            b2 = __reduce_add_sync(0xffffffffu, b2);
            b3 = __reduce_add_sync(0xffffffffu, b3);
        }
        if (lane == 0) {
            if (p < T_LEN) {
                float gi  = (float)a0 * fs1.x + p0;
                float gf_ = (float)a1 * fs1.y + p1;
                float gg  = (float)a2 * fs1.z + p2;
                float go_ = (float)a3 * fs1.w + p3;
                c1 = sigf(gf_) * c1 + sigf(gi) * tanhfast(gg);
                float h = sigf(go_) * tanhfast(c1);
                g_h1q[(p + 1) & 1][w] = (signed char)__float2int_rn(h * 127.f);
            }
            if (p >= 1) {
                float gi  = (float)b0 * fs2.x + bi;
                float gf_ = (float)b1 * fs2.y + bf;
                float gg  = (float)b2 * fs2.z + bg;
                float go_ = (float)b3 * fs2.w + bo;
                c2 = sigf(gf_) * c2 + sigf(gi) * tanhfast(gg);
                float h = sigf(go_) * tanhfast(c2);
                g_h2q[p & 1][w] = (signed char)__float2int_rn(h * 127.f);
                if (p == T_LEN) g_h2f[w] = h;
            }
        }

        // -------- grid barrier: fence + atomicAdd arrive, single-word acquire poll --------
        __syncthreads();
        if (tid == 0) {
            __threadfence();                         // release: publish h-state stores
            atomicAdd(&g_count, 1u);
            unsigned tgt = (unsigned)(p + 1) * (unsigned)NCTA;
            while (ld_acq(&g_count) < tgt) { }
        }
        __syncthreads();
    }
}

// ---------------- K3a: tag_space = h2 @ W_out^T + b_out (one block per tag) ----------------
__global__ void k3a(const float* __restrict__ Wout, const float* __restrict__ bout) {
    __shared__ float red[256];
    const int b = blockIdx.x, t = threadIdx.x;
    float acc = 0.f;
    #pragma unroll
    for (int c = 0; c < 2; c++) {
        float4 wv = *(const float4*)(Wout + (size_t)b * H_DIM + c * 1024 + t * 4);
        float4 hv = *(const float4*)(g_h2f + c * 1024 + t * 4);
        acc += wv.x * hv.x + wv.y * hv.y + wv.z * hv.z + wv.w * hv.w;
    }
    red[t] = acc;
    __syncthreads();
    #pragma unroll
    for (int s = 128; s; s >>= 1) {
        if (t < s) red[t] += red[t + s];
        __syncthreads();
    }
    if (t == 0) g_tag[b] = red[0] + bout[b];
}

// ---------------- K3b: log_softmax ----------------
__global__ void k3b(float* __restrict__ out) {
    __shared__ float st[NTAGS];
    __shared__ float m_s, l_s;
    const int t = threadIdx.x;
    float v = g_tag[t];
    st[t] = v;
    __syncthreads();
    if (t == 0) {
        float m = st[0];
        for (int i = 1; i < NTAGS; i++) m = fmaxf(m, st[i]);
        float s = 0.f;
        for (int i = 0; i < NTAGS; i++) s += expf(st[i] - m);
        m_s = m;
        l_s = logf(s);
    }
    __syncthreads();
    out[t] = v - m_s - l_s;
}

// ---------------- launch ----------------
extern "C" void kernel_launch(void* const* d_in, const int* in_sizes, int n_in,
                              void* d_out, int out_size) {
    const float* x    = (const float*)d_in[0];
    const float* Wih1 = (const float*)d_in[1];
    const float* Whh1 = (const float*)d_in[2];
    const float* bih1 = (const float*)d_in[3];
    const float* bhh1 = (const float*)d_in[4];
    const float* Wih2 = (const float*)d_in[5];
    const float* Whh2 = (const float*)d_in[6];
    const float* bih2 = (const float*)d_in[7];
    const float* bhh2 = (const float*)d_in[8];
    const float* Wout = (const float*)d_in[9];
    const float* bout = (const float*)d_in[10];

    cudaFuncSetAttribute(k2_recur, cudaFuncAttributeMaxDynamicSharedMemorySize, SMEM_BYTES);

    k0_quant<<<512, 256>>>(Whh1, Wih2, Whh2, bih2, bhh2);

    dim3 g1(G4 / 128, T_LEN / 128);
    k1_mma<<<g1, 256>>>(x, Wih1, bih1, bhh1);

    k2_recur<<<NCTA, NTHR, SMEM_BYTES>>>();

    k3a<<<NTAGS, 256>>>(Wout, bout);
    k3b<<<1, NTAGS>>>((float*)d_out);
}